// round 2
// baseline (speedup 1.0000x reference)
#include <cuda_runtime.h>
#include <math.h>

#define BB 2
#define NN 10000
#define EE 160000
#define DD 128
#define DIN 5
#define NLAYERS 4
#define BN (BB*NN)
#define NEGS 0.2f
#define EPSF 1e-5f

// ---------------- scratch (device globals: no allocation allowed) ------------
__device__ float g_h[BN*DD];      // node features
__device__ float g_P[BN*DD];      // h @ W1a   (later reused as aggr@W2 result)
__device__ float g_Q[BN*DD];      // h @ W1b   (later reused as gc z1)
__device__ float g_aggr[BN*DD];   // scatter accumulator (pre-W2)
__device__ int   g_deg[NN];
__device__ float g_gs[BB*DD];
__device__ float g_gate[BB*DD];

__device__ __forceinline__ float lrelu(float x){ return x > 0.f ? x : NEGS*x; }

// ---------------- encoder: h = x @ enc_W + enc_b -----------------------------
__global__ void k_encoder(const float* __restrict__ x, const float* __restrict__ W,
                          const float* __restrict__ b){
  int bn = blockIdx.x; int d = threadIdx.x;
  float acc = b[d];
  #pragma unroll
  for (int i = 0; i < DIN; i++) acc += x[bn*DIN + i] * W[i*DD + d];
  g_h[(size_t)bn*DD + d] = acc;
}

// ---------------- degree counts ----------------------------------------------
__global__ void k_deg(const int* __restrict__ ei){
  int e = blockIdx.x*blockDim.x + threadIdx.x;
  if (e < EE) atomicAdd(&g_deg[ei[e]], 1);
}

// ---------------- generic node GEMV tile kernel ------------------------------
// out[node] = epilogue( in[node] @ W (+ bias) ), W in [128,128] row-major.
// 256 threads: d = t&127 output dim, sub = t>>7 picks half the 8-node tile.
// EPI: 0 = store, 1 = accumulate into gs[b*DD+d] (global-context mean), 2 = +deg*bias store
#define NT 8
template<bool LRELU_F, int EPI>
__global__ void k_gemm128(const float* __restrict__ in, const float* __restrict__ W,
                          const float* __restrict__ bias, float* __restrict__ out,
                          const int* __restrict__ deg){
  extern __shared__ float sm[];
  float* sW  = sm;             // 128*128
  float* sIn = sm + DD*DD;     // NT*128
  const int t = threadIdx.x, d = t & (DD-1), sub = t >> 7;
  for (int i = t; i < DD*DD; i += 256) sW[i] = W[i];
  __syncthreads();
  float gsacc0 = 0.f, gsacc1 = 0.f;
  const int ntiles = BN / NT;
  for (int tile = blockIdx.x; tile < ntiles; tile += gridDim.x){
    const int node0 = tile * NT;
    {
      const float4* src = (const float4*)(in + (size_t)node0*DD);
      float4* dst = (float4*)sIn;
      #pragma unroll
      for (int i = t; i < NT*DD/4; i += 256) dst[i] = src[i];
    }
    __syncthreads();
    float acc[NT/2];
    #pragma unroll
    for (int j = 0; j < NT/2; j++) acc[j] = 0.f;
    #pragma unroll 8
    for (int k = 0; k < DD; k += 4){
      const float w0 = sW[k*DD+d], w1 = sW[(k+1)*DD+d];
      const float w2 = sW[(k+2)*DD+d], w3 = sW[(k+3)*DD+d];
      #pragma unroll
      for (int j = 0; j < NT/2; j++){
        const float4 v = *(const float4*)(sIn + (sub*(NT/2)+j)*DD + k);
        acc[j] += w0*v.x + w1*v.y + w2*v.z + w3*v.w;
      }
    }
    if (EPI == 1){
      float s = 0.f;
      #pragma unroll
      for (int j = 0; j < NT/2; j++) s += acc[j] + bias[d];
      if (node0 < NN) gsacc0 += s; else gsacc1 += s;
    } else {
      #pragma unroll
      for (int j = 0; j < NT/2; j++){
        const int node = node0 + sub*(NT/2) + j;
        float v = acc[j];
        if (EPI == 2) v += (float)deg[node % NN] * bias[d];
        else if (bias) v += bias[d];
        if (LRELU_F) v = lrelu(v);
        out[(size_t)node*DD + d] = v;
      }
    }
    __syncthreads();
  }
  if (EPI == 1){
    atomicAdd(&out[d], gsacc0);
    atomicAdd(&out[DD + d], gsacc1);
  }
}

// ---------------- edge kernel: t = lrelu(P[row]+Q[col]+ea@W1c+b1); LN; scatter
__global__ void k_edges(const int* __restrict__ ei, const float* __restrict__ ea,
                        const float* __restrict__ W1c, const float* __restrict__ b1,
                        const float* __restrict__ lg, const float* __restrict__ lb){
  const int w = (blockIdx.x*blockDim.x + threadIdx.x) >> 5;
  if (w >= BB*EE) return;
  const int lane = threadIdx.x & 31;
  const int b = w / EE, e = w - b*EE;
  const int r = __ldg(&ei[e]);
  const int c = __ldg(&ei[EE + e]);
  const float ea0 = __ldg(&ea[2*e]), ea1 = __ldg(&ea[2*e + 1]);
  const float4 p  = ((const float4*)(g_P + (size_t)(b*NN + r)*DD))[lane];
  const float4 q  = ((const float4*)(g_Q + (size_t)(b*NN + c)*DD))[lane];
  const float4 w0 = ((const float4*)W1c)[lane];
  const float4 w1 = ((const float4*)(W1c + DD))[lane];
  const float4 bv = ((const float4*)b1)[lane];
  float t0 = lrelu(p.x + q.x + ea0*w0.x + ea1*w1.x + bv.x);
  float t1 = lrelu(p.y + q.y + ea0*w0.y + ea1*w1.y + bv.y);
  float t2 = lrelu(p.z + q.z + ea0*w0.z + ea1*w1.z + bv.z);
  float t3 = lrelu(p.w + q.w + ea0*w0.w + ea1*w1.w + bv.w);
  float s = t0 + t1 + t2 + t3;
  #pragma unroll
  for (int o = 16; o; o >>= 1) s += __shfl_xor_sync(0xffffffffu, s, o);
  const float mu = s * (1.f/DD);
  const float c0 = t0-mu, c1 = t1-mu, c2 = t2-mu, c3 = t3-mu;
  float sq = c0*c0 + c1*c1 + c2*c2 + c3*c3;
  #pragma unroll
  for (int o = 16; o; o >>= 1) sq += __shfl_xor_sync(0xffffffffu, sq, o);
  const float rs = rsqrtf(sq*(1.f/DD) + EPSF);
  const float4 gv = ((const float4*)lg)[lane];
  const float4 bt = ((const float4*)lb)[lane];
  float* dst = g_aggr + (size_t)(b*NN + r)*DD + lane*4;
  atomicAdd(dst + 0, c0*rs*gv.x + bt.x);
  atomicAdd(dst + 1, c1*rs*gv.y + bt.y);
  atomicAdd(dst + 2, c2*rs*gv.z + bt.z);
  atomicAdd(dst + 3, c3*rs*gv.w + bt.w);
}

// ---------------- node update: h += LN(lrelu([h,aggr2] @ uW + ub)) -----------
#define NT2 4
__global__ void k_update(const float* __restrict__ aggr2, const float* __restrict__ uW,
                         const float* __restrict__ ub, const float* __restrict__ lg,
                         const float* __restrict__ lb){
  extern __shared__ float sm[];
  float* sW   = sm;                     // 256*128
  float* sIn  = sW + 256*DD;            // NT2*256
  float* sU   = sIn + NT2*256;          // NT2*128
  float* sRed = sU + NT2*DD;            // NT2*2
  const int t = threadIdx.x, d = t & 127, sub = t >> 7;
  const int lane = t & 31, warp = t >> 5;
  for (int i = t; i < 256*DD; i += 256) sW[i] = uW[i];
  __syncthreads();
  const int ntiles = BN / NT2;
  for (int tile = blockIdx.x; tile < ntiles; tile += gridDim.x){
    const int node0 = tile * NT2;
    {
      const float4* hs = (const float4*)(g_h   + (size_t)node0*DD);
      const float4* as = (const float4*)(aggr2 + (size_t)node0*DD);
      for (int i = t; i < NT2*DD/4; i += 256){
        const int nl = i / (DD/4), k4 = i % (DD/4);
        ((float4*)(sIn + nl*256))[k4]      = hs[i];
        ((float4*)(sIn + nl*256 + DD))[k4] = as[i];
      }
    }
    __syncthreads();
    float acc0 = 0.f, acc1 = 0.f;
    #pragma unroll 8
    for (int k = 0; k < 256; k += 4){
      const float w0 = sW[k*DD+d], w1 = sW[(k+1)*DD+d];
      const float w2 = sW[(k+2)*DD+d], w3 = sW[(k+3)*DD+d];
      const float4 v0 = *(const float4*)(sIn + (sub*2+0)*256 + k);
      const float4 v1 = *(const float4*)(sIn + (sub*2+1)*256 + k);
      acc0 += w0*v0.x + w1*v0.y + w2*v0.z + w3*v0.w;
      acc1 += w0*v1.x + w1*v1.y + w2*v1.z + w3*v1.w;
    }
    const float bv = ub[d];
    sU[(sub*2+0)*DD + d] = lrelu(acc0 + bv);
    sU[(sub*2+1)*DD + d] = lrelu(acc1 + bv);
    __syncthreads();
    if (warp < NT2){
      const float4 v = ((const float4*)(sU + warp*DD))[lane];
      float s = v.x + v.y + v.z + v.w;
      #pragma unroll
      for (int o = 16; o; o >>= 1) s += __shfl_xor_sync(0xffffffffu, s, o);
      const float mu = s * (1.f/DD);
      const float c0 = v.x-mu, c1 = v.y-mu, c2 = v.z-mu, c3 = v.w-mu;
      float sq = c0*c0 + c1*c1 + c2*c2 + c3*c3;
      #pragma unroll
      for (int o = 16; o; o >>= 1) sq += __shfl_xor_sync(0xffffffffu, sq, o);
      if (lane == 0){ sRed[warp*2] = mu; sRed[warp*2+1] = rsqrtf(sq*(1.f/DD) + EPSF); }
    }
    __syncthreads();
    const float gv = lg[d], bvv = lb[d];
    #pragma unroll
    for (int j = 0; j < 2; j++){
      const int nl = sub*2 + j;
      const float mu = sRed[nl*2], rs = sRed[nl*2+1];
      g_h[(size_t)(node0+nl)*DD + d] += (sU[nl*DD + d] - mu)*rs*gv + bvv;
    }
    __syncthreads();
  }
}

// ---------------- gate: gate = sigmoid((gs/N) @ Wc + bc) ---------------------
__global__ void k_gate(const float* __restrict__ Wc, const float* __restrict__ bc){
  const int b = blockIdx.x, d = threadIdx.x;
  __shared__ float s[DD];
  s[d] = g_gs[b*DD + d] * (1.f/NN);
  __syncthreads();
  float acc = bc[d];
  #pragma unroll 8
  for (int k = 0; k < DD; k++) acc += s[k] * Wc[k*DD + d];
  g_gate[b*DD + d] = 1.f/(1.f + expf(-acc));
}

__global__ void k_scale(){
  const int i = blockIdx.x*blockDim.x + threadIdx.x;
  if (i < BN*DD){
    const int b = i / (NN*DD);
    g_h[i] *= g_gate[b*DD + (i & (DD-1))];
  }
}

// ---------------- decoder ----------------------------------------------------
__global__ void k_dec(const float* __restrict__ W1, const float* __restrict__ b1,
                      const float* __restrict__ W2, const float* __restrict__ b2,
                      float* __restrict__ out){
  __shared__ float sh[DD];
  __shared__ float sred[2][2];
  const int node = blockIdx.x, t = threadIdx.x;       // 64 threads
  sh[t]      = g_h[(size_t)node*DD + t];
  sh[t + 64] = g_h[(size_t)node*DD + t + 64];
  __syncthreads();
  float acc = b1[t];
  #pragma unroll 8
  for (int k = 0; k < DD; k++) acc += sh[k] * W1[k*64 + t];
  acc = lrelu(acc);
  float o0 = acc * W2[t*2], o1 = acc * W2[t*2 + 1];
  #pragma unroll
  for (int o = 16; o; o >>= 1){
    o0 += __shfl_xor_sync(0xffffffffu, o0, o);
    o1 += __shfl_xor_sync(0xffffffffu, o1, o);
  }
  const int warp = t >> 5;
  if ((t & 31) == 0){ sred[warp][0] = o0; sred[warp][1] = o1; }
  __syncthreads();
  if (t == 0){
    out[(size_t)node*2]     = sred[0][0] + sred[1][0] + b2[0];
    out[(size_t)node*2 + 1] = sred[0][1] + sred[1][1] + b2[1];
  }
}

// ---------------- host -------------------------------------------------------
extern "C" void kernel_launch(void* const* d_in, const int* in_sizes, int n_in,
                              void* d_out, int out_size){
  const float* x      = (const float*)d_in[0];
  const float* ea     = (const float*)d_in[1];
  const int*   ei     = (const int*)  d_in[2];
  const float* enc_W  = (const float*)d_in[3];
  const float* enc_b  = (const float*)d_in[4];
  const float* msg_W1 = (const float*)d_in[5];
  const float* msg_b1 = (const float*)d_in[6];
  const float* msg_lg = (const float*)d_in[7];
  const float* msg_lb = (const float*)d_in[8];
  const float* msg_W2 = (const float*)d_in[9];
  const float* msg_b2 = (const float*)d_in[10];
  const float* up_W   = (const float*)d_in[11];
  const float* up_b   = (const float*)d_in[12];
  const float* up_lg  = (const float*)d_in[13];
  const float* up_lb  = (const float*)d_in[14];
  const float* gc_Wa  = (const float*)d_in[15];
  const float* gc_ba  = (const float*)d_in[16];
  const float* gc_Wb  = (const float*)d_in[17];
  const float* gc_bb  = (const float*)d_in[18];
  const float* gc_Wc  = (const float*)d_in[19];
  const float* gc_bc  = (const float*)d_in[20];
  const float* dec_W1 = (const float*)d_in[21];
  const float* dec_b1 = (const float*)d_in[22];
  const float* dec_W2 = (const float*)d_in[23];
  const float* dec_b2 = (const float*)d_in[24];
  float* out = (float*)d_out;

  void *p_h, *p_P, *p_Q, *p_aggr, *p_gs, *p_deg;
  cudaGetSymbolAddress(&p_h, g_h);
  cudaGetSymbolAddress(&p_P, g_P);
  cudaGetSymbolAddress(&p_Q, g_Q);
  cudaGetSymbolAddress(&p_aggr, g_aggr);
  cudaGetSymbolAddress(&p_gs, g_gs);
  cudaGetSymbolAddress(&p_deg, g_deg);

  const int SMEM_G = (DD*DD + NT*DD) * 4;                      // 69632 B
  const int SMEM_U = (256*DD + NT2*256 + NT2*DD + 2*NT2) * 4;  // ~137 KB
  cudaFuncSetAttribute(k_gemm128<false,0>, cudaFuncAttributeMaxDynamicSharedMemorySize, SMEM_G);
  cudaFuncSetAttribute(k_gemm128<true, 0>, cudaFuncAttributeMaxDynamicSharedMemorySize, SMEM_G);
  cudaFuncSetAttribute(k_gemm128<false,1>, cudaFuncAttributeMaxDynamicSharedMemorySize, SMEM_G);
  cudaFuncSetAttribute(k_gemm128<false,2>, cudaFuncAttributeMaxDynamicSharedMemorySize, SMEM_G);
  cudaFuncSetAttribute(k_update,           cudaFuncAttributeMaxDynamicSharedMemorySize, SMEM_U);

  cudaMemsetAsync(p_deg, 0, NN*sizeof(int), 0);
  k_encoder<<<BN, DD>>>(x, enc_W, enc_b);
  k_deg<<<(EE + 255)/256, 256>>>(ei);

  for (int l = 0; l < NLAYERS; l++){
    const float* W1  = msg_W1 + (size_t)l*258*DD;
    const float* W1a = W1;
    const float* W1b = W1 + 128*DD;
    const float* W1c = W1 + 256*DD;
    const float* b1  = msg_b1 + l*DD;
    const float* mlg = msg_lg + l*DD;
    const float* mlb = msg_lb + l*DD;
    const float* W2  = msg_W2 + (size_t)l*DD*DD;
    const float* b2  = msg_b2 + l*DD;
    const float* uWl = up_W  + (size_t)l*256*DD;
    const float* ubl = up_b  + l*DD;
    const float* ulg = up_lg + l*DD;
    const float* ulb = up_lb + l*DD;
    const float* Wa  = gc_Wa + (size_t)l*DD*DD;
    const float* ba  = gc_ba + l*DD;
    const float* Wb  = gc_Wb + (size_t)l*DD*DD;
    const float* bbv = gc_bb + l*DD;
    const float* Wc  = gc_Wc + (size_t)l*DD*DD;
    const float* bc  = gc_bc + l*DD;

    cudaMemsetAsync(p_aggr, 0, (size_t)BN*DD*sizeof(float), 0);
    cudaMemsetAsync(p_gs,   0, BB*DD*sizeof(float), 0);

    k_gemm128<false,0><<<444, 256, SMEM_G>>>((const float*)p_h, W1a, nullptr, (float*)p_P, nullptr);
    k_gemm128<false,0><<<444, 256, SMEM_G>>>((const float*)p_h, W1b, nullptr, (float*)p_Q, nullptr);
    k_edges<<<(BB*EE)/16, 512>>>(ei, ea, W1c, b1, mlg, mlb);
    k_gemm128<false,2><<<444, 256, SMEM_G>>>((const float*)p_aggr, W2, b2, (float*)p_P, (const int*)p_deg);
    k_update<<<148, 256, SMEM_U>>>((const float*)p_P, uWl, ubl, ulg, ulb);
    k_gemm128<true, 0><<<444, 256, SMEM_G>>>((const float*)p_h, Wa, ba, (float*)p_Q, nullptr);
    k_gemm128<false,1><<<444, 256, SMEM_G>>>((const float*)p_Q, Wb, bbv, (float*)p_gs, nullptr);
    k_gate<<<BB, DD>>>(Wc, bc);
    k_scale<<<(BN*DD + 255)/256, 256>>>();
  }

  k_dec<<<BN, 64>>>(dec_W1, dec_b1, dec_W2, dec_b2, out);
}

// round 3
// speedup vs baseline: 1.5234x; 1.5234x over previous
#include <cuda_runtime.h>
#include <math.h>

#define BB 2
#define NN 10000
#define EE 160000
#define DD 128
#define DIN 5
#define NLAYERS 4
#define BN (BB*NN)
#define NEGS 0.2f
#define EPSF 1e-5f
#define TILE 32
#define WPAD 132   // padded W row stride (floats) -> conflict-free float4 loads

// ---------------- scratch (device globals) -----------------------------------
__device__ float g_h[BN*DD];
__device__ float g_P[BN*DD];
__device__ float g_Q[BN*DD];
__device__ float g_aggr[BN*DD];
__device__ int   g_deg[NN];
__device__ int   g_row_off[NN+1];
__device__ int   g_cur[NN];
__device__ int   g_csr_col[EE];
__device__ float2 g_csr_ea[EE];
__device__ float g_gs[BB*DD];
__device__ float g_gate[BB*DD];

__device__ __forceinline__ float lrelu(float x){ return x > 0.f ? x : NEGS*x; }

__device__ __forceinline__ void fma4(float4& acc, const float4 x,
                                     const float4 w0, const float4 w1,
                                     const float4 w2, const float4 w3){
  acc.x += x.x*w0.x + x.y*w1.x + x.z*w2.x + x.w*w3.x;
  acc.y += x.x*w0.y + x.y*w1.y + x.z*w2.y + x.w*w3.y;
  acc.z += x.x*w0.z + x.y*w1.z + x.z*w2.z + x.w*w3.z;
  acc.w += x.x*w0.w + x.y*w1.w + x.z*w2.w + x.w*w3.w;
}

// ---------------- encoder ----------------------------------------------------
__global__ void k_encoder(const float* __restrict__ x, const float* __restrict__ W,
                          const float* __restrict__ b){
  int bn = blockIdx.x; int d = threadIdx.x;
  float acc = b[d];
  #pragma unroll
  for (int i = 0; i < DIN; i++) acc += x[bn*DIN + i] * W[i*DD + d];
  g_h[(size_t)bn*DD + d] = acc;
}

// ---------------- CSR build --------------------------------------------------
__global__ void k_deg(const int* __restrict__ ei){
  int e = blockIdx.x*blockDim.x + threadIdx.x;
  if (e < EE) atomicAdd(&g_deg[ei[e]], 1);
}

__global__ void k_scan(){   // 1 block, 1024 threads: deg -> row_off (exclusive), cur
  __shared__ int ssum[1024];
  const int t = threadIdx.x;
  const int base = t*10;
  int local[10];
  int s = 0;
  #pragma unroll
  for (int j = 0; j < 10; j++){
    int idx = base + j;
    int v = (idx < NN) ? g_deg[idx] : 0;
    local[j] = s; s += v;
  }
  ssum[t] = s;
  __syncthreads();
  for (int o = 1; o < 1024; o <<= 1){
    int v = (t >= o) ? ssum[t-o] : 0;
    __syncthreads();
    ssum[t] += v;
    __syncthreads();
  }
  int prefix = t ? ssum[t-1] : 0;
  #pragma unroll
  for (int j = 0; j < 10; j++){
    int idx = base + j;
    if (idx < NN){ g_row_off[idx] = prefix + local[j]; g_cur[idx] = prefix + local[j]; }
  }
  if (t == 0) g_row_off[NN] = EE;
}

__global__ void k_scatter(const int* __restrict__ ei, const float* __restrict__ ea){
  int e = blockIdx.x*blockDim.x + threadIdx.x;
  if (e >= EE) return;
  int r = ei[e];
  int pos = atomicAdd(&g_cur[r], 1);
  g_csr_col[pos] = ei[EE + e];
  g_csr_ea[pos] = make_float2(ea[2*e], ea[2*e+1]);
}

// ---------------- dual GEMM: P = h@WA, Q = h@WB ------------------------------
__global__ __launch_bounds__(256,1) void k_gemmPQ(const float* __restrict__ h,
    const float* __restrict__ WA, const float* __restrict__ WB,
    float* __restrict__ P, float* __restrict__ Q){
  extern __shared__ float sm[];
  float* sWA = sm;                 // 128*132
  float* sWB = sm + DD*WPAD;       // 128*132
  float* sIn = sWB + DD*WPAD;      // 32*128
  const int t = threadIdx.x;
  const int dG = t & 31, nG = t >> 5;
  const int d0 = dG << 2;
  for (int i = t; i < DD*DD; i += 256){
    int k = i >> 7, d = i & 127;
    sWA[k*WPAD + d] = WA[i];
    sWB[k*WPAD + d] = WB[i];
  }
  __syncthreads();
  for (int tile = blockIdx.x; tile < BN/TILE; tile += gridDim.x){
    const int node0 = tile * TILE;
    { const float4* src = (const float4*)(h + (size_t)node0*DD);
      float4* dst = (float4*)sIn;
      for (int i = t; i < TILE*DD/4; i += 256) dst[i] = src[i]; }
    __syncthreads();
    float4 accA[4], accB[4];
    #pragma unroll
    for (int j = 0; j < 4; j++){ accA[j] = make_float4(0,0,0,0); accB[j] = make_float4(0,0,0,0); }
    #pragma unroll 4
    for (int k = 0; k < DD; k += 4){
      const float4 a0 = *(const float4*)(sWA + (k+0)*WPAD + d0);
      const float4 a1 = *(const float4*)(sWA + (k+1)*WPAD + d0);
      const float4 a2 = *(const float4*)(sWA + (k+2)*WPAD + d0);
      const float4 a3 = *(const float4*)(sWA + (k+3)*WPAD + d0);
      const float4 b0 = *(const float4*)(sWB + (k+0)*WPAD + d0);
      const float4 b1 = *(const float4*)(sWB + (k+1)*WPAD + d0);
      const float4 b2 = *(const float4*)(sWB + (k+2)*WPAD + d0);
      const float4 b3 = *(const float4*)(sWB + (k+3)*WPAD + d0);
      #pragma unroll
      for (int j = 0; j < 4; j++){
        const float4 x = *(const float4*)(sIn + ((nG<<2)+j)*DD + k);
        fma4(accA[j], x, a0, a1, a2, a3);
        fma4(accB[j], x, b0, b1, b2, b3);
      }
    }
    #pragma unroll
    for (int j = 0; j < 4; j++){
      const int node = node0 + (nG<<2) + j;
      *(float4*)(P + (size_t)node*DD + d0) = accA[j];
      *(float4*)(Q + (size_t)node*DD + d0) = accB[j];
    }
    __syncthreads();
  }
}

// ---------------- GEMM: out = aggr@W2 + deg*b2 -------------------------------
__global__ __launch_bounds__(256,1) void k_gemmW2(const float* __restrict__ in,
    const float* __restrict__ W, const float* __restrict__ bias,
    float* __restrict__ out){
  extern __shared__ float sm[];
  float* sW  = sm;             // 128*132
  float* sIn = sm + DD*WPAD;   // 32*128
  const int t = threadIdx.x;
  const int dG = t & 31, nG = t >> 5;
  const int d0 = dG << 2;
  const float4 bv = ((const float4*)bias)[dG];
  for (int i = t; i < DD*DD; i += 256){
    int k = i >> 7, d = i & 127;
    sW[k*WPAD + d] = W[i];
  }
  __syncthreads();
  for (int tile = blockIdx.x; tile < BN/TILE; tile += gridDim.x){
    const int node0 = tile * TILE;
    { const float4* src = (const float4*)(in + (size_t)node0*DD);
      float4* dst = (float4*)sIn;
      for (int i = t; i < TILE*DD/4; i += 256) dst[i] = src[i]; }
    __syncthreads();
    float4 acc[4];
    #pragma unroll
    for (int j = 0; j < 4; j++) acc[j] = make_float4(0,0,0,0);
    #pragma unroll 4
    for (int k = 0; k < DD; k += 4){
      const float4 w0 = *(const float4*)(sW + (k+0)*WPAD + d0);
      const float4 w1 = *(const float4*)(sW + (k+1)*WPAD + d0);
      const float4 w2 = *(const float4*)(sW + (k+2)*WPAD + d0);
      const float4 w3 = *(const float4*)(sW + (k+3)*WPAD + d0);
      #pragma unroll
      for (int j = 0; j < 4; j++){
        const float4 x = *(const float4*)(sIn + ((nG<<2)+j)*DD + k);
        fma4(acc[j], x, w0, w1, w2, w3);
      }
    }
    #pragma unroll
    for (int j = 0; j < 4; j++){
      const int node = node0 + (nG<<2) + j;
      const float dg = (float)g_deg[node % NN];
      float4 v = acc[j];
      v.x += dg*bv.x; v.y += dg*bv.y; v.z += dg*bv.z; v.w += dg*bv.w;
      *(float4*)(out + (size_t)node*DD + d0) = v;
    }
    __syncthreads();
  }
}

// ---------------- CSR aggregation (no atomics) -------------------------------
__global__ void k_aggregate(const float* __restrict__ P, const float* __restrict__ Q,
                            const float* __restrict__ W1c, const float* __restrict__ b1,
                            const float* __restrict__ lg, const float* __restrict__ lb,
                            float* __restrict__ aggr){
  const int w = (blockIdx.x*blockDim.x + threadIdx.x) >> 5;
  if (w >= BB*NN) return;
  const int lane = threadIdx.x & 31;
  const int b = w / NN, n = w - b*NN;
  const int off = g_row_off[n], end = g_row_off[n+1];
  const int bN = b*NN;
  const float4* Qv = (const float4*)Q;
  const float4 p  = ((const float4*)(P + (size_t)(bN + n)*DD))[lane];
  const float4 w0 = ((const float4*)W1c)[lane];
  const float4 w1 = ((const float4*)(W1c + DD))[lane];
  const float4 bv = ((const float4*)b1)[lane];
  const float4 gv = ((const float4*)lg)[lane];
  const float4 bt = ((const float4*)lb)[lane];
  float4 acc = make_float4(0,0,0,0);
  int ncol = 0; float2 nea = make_float2(0,0); float4 q = make_float4(0,0,0,0);
  if (off < end){
    ncol = g_csr_col[off]; nea = g_csr_ea[off];
    q = Qv[(size_t)(bN + ncol)*32 + lane];
  }
  for (int i = off; i < end; i++){
    const float4 qc = q; const float2 ec = nea;
    if (i + 1 < end){
      ncol = g_csr_col[i+1]; nea = g_csr_ea[i+1];
      q = Qv[(size_t)(bN + ncol)*32 + lane];
    }
    const float t0 = lrelu(p.x + qc.x + ec.x*w0.x + ec.y*w1.x + bv.x);
    const float t1 = lrelu(p.y + qc.y + ec.x*w0.y + ec.y*w1.y + bv.y);
    const float t2 = lrelu(p.z + qc.z + ec.x*w0.z + ec.y*w1.z + bv.z);
    const float t3 = lrelu(p.w + qc.w + ec.x*w0.w + ec.y*w1.w + bv.w);
    float s  = t0 + t1 + t2 + t3;
    float sq = t0*t0 + t1*t1 + t2*t2 + t3*t3;
    #pragma unroll
    for (int o = 16; o; o >>= 1){
      s  += __shfl_xor_sync(0xffffffffu, s,  o);
      sq += __shfl_xor_sync(0xffffffffu, sq, o);
    }
    const float mu = s * (1.f/DD);
    const float var = sq * (1.f/DD) - mu*mu;
    const float rs = rsqrtf(var + EPSF);
    acc.x += (t0 - mu)*rs*gv.x + bt.x;
    acc.y += (t1 - mu)*rs*gv.y + bt.y;
    acc.z += (t2 - mu)*rs*gv.z + bt.z;
    acc.w += (t3 - mu)*rs*gv.w + bt.w;
  }
  ((float4*)(aggr + (size_t)(bN + n)*DD))[lane] = acc;
}

// ---------------- node update: h += LN(lrelu([h,aggr2]@uW + ub)) -------------
__global__ __launch_bounds__(256,1) void k_update(const float* __restrict__ aggr2,
    const float* __restrict__ uW, const float* __restrict__ ub,
    const float* __restrict__ lg, const float* __restrict__ lb){
  extern __shared__ float sm[];
  float* sW  = sm;               // 256*132
  float* sIn = sm + 256*WPAD;    // 32*256
  float* sU  = sIn + TILE*256;   // 32*128
  const int t = threadIdx.x;
  const int dG = t & 31, nG = t >> 5;
  const int d0 = dG << 2;
  const int lane = t & 31, warp = t >> 5;
  for (int i = t; i < 256*DD; i += 256){
    int k = i >> 7, d = i & 127;
    sW[k*WPAD + d] = uW[i];
  }
  const float4 ubv = ((const float4*)ub)[dG];
  __syncthreads();
  for (int tile = blockIdx.x; tile < BN/TILE; tile += gridDim.x){
    const int node0 = tile * TILE;
    { const float4* hs = (const float4*)(g_h   + (size_t)node0*DD);
      const float4* as = (const float4*)(aggr2 + (size_t)node0*DD);
      for (int i = t; i < TILE*DD/4; i += 256){
        const int nl = i >> 5, k4 = i & 31;
        ((float4*)(sIn + nl*256))[k4]       = hs[i];
        ((float4*)(sIn + nl*256 + DD))[k4]  = as[i];
      }
    }
    __syncthreads();
    float4 acc[4];
    #pragma unroll
    for (int j = 0; j < 4; j++) acc[j] = make_float4(0,0,0,0);
    #pragma unroll 4
    for (int k = 0; k < 256; k += 4){
      const float4 w0 = *(const float4*)(sW + (k+0)*WPAD + d0);
      const float4 w1 = *(const float4*)(sW + (k+1)*WPAD + d0);
      const float4 w2 = *(const float4*)(sW + (k+2)*WPAD + d0);
      const float4 w3 = *(const float4*)(sW + (k+3)*WPAD + d0);
      #pragma unroll
      for (int j = 0; j < 4; j++){
        const float4 x = *(const float4*)(sIn + ((nG<<2)+j)*256 + k);
        fma4(acc[j], x, w0, w1, w2, w3);
      }
    }
    #pragma unroll
    for (int j = 0; j < 4; j++){
      float4 v = acc[j];
      v.x = lrelu(v.x + ubv.x); v.y = lrelu(v.y + ubv.y);
      v.z = lrelu(v.z + ubv.z); v.w = lrelu(v.w + ubv.w);
      *(float4*)(sU + ((nG<<2)+j)*DD + d0) = v;
    }
    __syncthreads();
    // LN + residual: warp handles 4 nodes
    #pragma unroll
    for (int j = 0; j < 4; j++){
      const int nl = (warp<<2) + j;
      const float4 v = ((const float4*)(sU + nl*DD))[lane];
      float s  = v.x + v.y + v.z + v.w;
      float sq = v.x*v.x + v.y*v.y + v.z*v.z + v.w*v.w;
      #pragma unroll
      for (int o = 16; o; o >>= 1){
        s  += __shfl_xor_sync(0xffffffffu, s,  o);
        sq += __shfl_xor_sync(0xffffffffu, sq, o);
      }
      const float mu = s * (1.f/DD);
      const float rs = rsqrtf(sq*(1.f/DD) - mu*mu + EPSF);
      const float4 hv = ((const float4*)(sIn + nl*256))[lane];
      const float4 gvv = ((const float4*)lg)[lane];
      const float4 bvv = ((const float4*)lb)[lane];
      float4 o4;
      o4.x = hv.x + (v.x - mu)*rs*gvv.x + bvv.x;
      o4.y = hv.y + (v.y - mu)*rs*gvv.y + bvv.y;
      o4.z = hv.z + (v.z - mu)*rs*gvv.z + bvv.z;
      o4.w = hv.w + (v.w - mu)*rs*gvv.w + bvv.w;
      ((float4*)(g_h + (size_t)(node0 + nl)*DD))[lane] = o4;
    }
    __syncthreads();
  }
}

// ---------------- global context fused: gs += sum_n lrelu(h@Wa+ba)@Wb --------
__global__ __launch_bounds__(256,1) void k_gc(const float* __restrict__ h,
    const float* __restrict__ Wa, const float* __restrict__ ba,
    const float* __restrict__ Wb){
  extern __shared__ float sm[];
  float* sWa = sm;                 // 128*132
  float* sWb = sm + DD*WPAD;       // 128*132
  float* sIn = sWb + DD*WPAD;      // 32*128
  float* sZ  = sIn + TILE*DD;      // 32*128
  const int t = threadIdx.x;
  const int dG = t & 31, nG = t >> 5;
  const int d0 = dG << 2;
  for (int i = t; i < DD*DD; i += 256){
    int k = i >> 7, d = i & 127;
    sWa[k*WPAD + d] = Wa[i];
    sWb[k*WPAD + d] = Wb[i];
  }
  const float4 bav = ((const float4*)ba)[dG];
  __syncthreads();
  float4 gs0 = make_float4(0,0,0,0), gs1 = make_float4(0,0,0,0);
  for (int tile = blockIdx.x; tile < BN/TILE; tile += gridDim.x){
    const int node0 = tile * TILE;
    { const float4* src = (const float4*)(h + (size_t)node0*DD);
      float4* dst = (float4*)sIn;
      for (int i = t; i < TILE*DD/4; i += 256) dst[i] = src[i]; }
    __syncthreads();
    // stage 1: z = lrelu(h@Wa + ba)
    {
      float4 acc[4];
      #pragma unroll
      for (int j = 0; j < 4; j++) acc[j] = make_float4(0,0,0,0);
      #pragma unroll 4
      for (int k = 0; k < DD; k += 4){
        const float4 w0 = *(const float4*)(sWa + (k+0)*WPAD + d0);
        const float4 w1 = *(const float4*)(sWa + (k+1)*WPAD + d0);
        const float4 w2 = *(const float4*)(sWa + (k+2)*WPAD + d0);
        const float4 w3 = *(const float4*)(sWa + (k+3)*WPAD + d0);
        #pragma unroll
        for (int j = 0; j < 4; j++){
          const float4 x = *(const float4*)(sIn + ((nG<<2)+j)*DD + k);
          fma4(acc[j], x, w0, w1, w2, w3);
        }
      }
      #pragma unroll
      for (int j = 0; j < 4; j++){
        float4 v = acc[j];
        v.x = lrelu(v.x + bav.x); v.y = lrelu(v.y + bav.y);
        v.z = lrelu(v.z + bav.z); v.w = lrelu(v.w + bav.w);
        *(float4*)(sZ + ((nG<<2)+j)*DD + d0) = v;
      }
    }
    __syncthreads();
    // stage 2: per-node z@Wb, accumulate by batch
    {
      float4 na[4];
      #pragma unroll
      for (int j = 0; j < 4; j++) na[j] = make_float4(0,0,0,0);
      #pragma unroll 4
      for (int k = 0; k < DD; k += 4){
        const float4 w0 = *(const float4*)(sWb + (k+0)*WPAD + d0);
        const float4 w1 = *(const float4*)(sWb + (k+1)*WPAD + d0);
        const float4 w2 = *(const float4*)(sWb + (k+2)*WPAD + d0);
        const float4 w3 = *(const float4*)(sWb + (k+3)*WPAD + d0);
        #pragma unroll
        for (int j = 0; j < 4; j++){
          const float4 z = *(const float4*)(sZ + ((nG<<2)+j)*DD + k);
          fma4(na[j], z, w0, w1, w2, w3);
        }
      }
      #pragma unroll
      for (int j = 0; j < 4; j++){
        const int node = node0 + (nG<<2) + j;
        if (node < NN){ gs0.x += na[j].x; gs0.y += na[j].y; gs0.z += na[j].z; gs0.w += na[j].w; }
        else          { gs1.x += na[j].x; gs1.y += na[j].y; gs1.z += na[j].z; gs1.w += na[j].w; }
      }
    }
    __syncthreads();
  }
  atomicAdd(&g_gs[d0+0], gs0.x); atomicAdd(&g_gs[d0+1], gs0.y);
  atomicAdd(&g_gs[d0+2], gs0.z); atomicAdd(&g_gs[d0+3], gs0.w);
  atomicAdd(&g_gs[DD+d0+0], gs1.x); atomicAdd(&g_gs[DD+d0+1], gs1.y);
  atomicAdd(&g_gs[DD+d0+2], gs1.z); atomicAdd(&g_gs[DD+d0+3], gs1.w);
}

// ---------------- gate: gate = sigmoid((gs/N + bb) @ Wc + bc) ----------------
__global__ void k_gate(const float* __restrict__ Wc, const float* __restrict__ bc,
                       const float* __restrict__ bb){
  const int b = blockIdx.x, d = threadIdx.x;
  __shared__ float s[DD];
  s[d] = g_gs[b*DD + d] * (1.f/NN) + bb[d];
  __syncthreads();
  float acc = bc[d];
  #pragma unroll 8
  for (int k = 0; k < DD; k++) acc += s[k] * Wc[k*DD + d];
  g_gate[b*DD + d] = 1.f/(1.f + expf(-acc));
}

__global__ void k_scale(){
  const int i = blockIdx.x*blockDim.x + threadIdx.x;
  if (i < BN*DD){
    const int b = i / (NN*DD);
    g_h[i] *= g_gate[b*DD + (i & (DD-1))];
  }
}

// ---------------- decoder (register-tiled) -----------------------------------
__global__ __launch_bounds__(256,1) void k_dec(const float* __restrict__ W1,
    const float* __restrict__ b1, const float* __restrict__ W2,
    const float* __restrict__ b2, float* __restrict__ out){
  extern __shared__ float sm[];
  float* sW1 = sm;               // 128*68
  float* sIn = sm + DD*68;       // 32*128
  float* sU  = sIn + TILE*DD;    // 32*64
  float* sW2 = sU + TILE*64;     // 128 + 2
  const int t = threadIdx.x;
  const int dG = t & 15, nG = t >> 4;   // 16 dim-groups (64 dims), 16 node-groups x 2
  const int d0 = dG << 2;
  const int lane = t & 31, warp = t >> 5;
  for (int i = t; i < DD*64; i += 256){
    int k = i >> 6, d = i & 63;
    sW1[k*68 + d] = W1[i];
  }
  if (t < 128) sW2[t] = W2[t];
  if (t < 2) sW2[128 + t] = b2[t];
  const float4 b1v = ((const float4*)b1)[dG];
  __syncthreads();
  for (int tile = blockIdx.x; tile < BN/TILE; tile += gridDim.x){
    const int node0 = tile * TILE;
    { const float4* src = (const float4*)(g_h + (size_t)node0*DD);
      float4* dst = (float4*)sIn;
      for (int i = t; i < TILE*DD/4; i += 256) dst[i] = src[i]; }
    __syncthreads();
    float4 acc[2];
    acc[0] = make_float4(0,0,0,0); acc[1] = make_float4(0,0,0,0);
    #pragma unroll 4
    for (int k = 0; k < DD; k += 4){
      const float4 w0 = *(const float4*)(sW1 + (k+0)*68 + d0);
      const float4 w1 = *(const float4*)(sW1 + (k+1)*68 + d0);
      const float4 w2 = *(const float4*)(sW1 + (k+2)*68 + d0);
      const float4 w3 = *(const float4*)(sW1 + (k+3)*68 + d0);
      #pragma unroll
      for (int j = 0; j < 2; j++){
        const float4 x = *(const float4*)(sIn + ((nG<<1)+j)*DD + k);
        fma4(acc[j], x, w0, w1, w2, w3);
      }
    }
    #pragma unroll
    for (int j = 0; j < 2; j++){
      float4 v = acc[j];
      v.x = lrelu(v.x + b1v.x); v.y = lrelu(v.y + b1v.y);
      v.z = lrelu(v.z + b1v.z); v.w = lrelu(v.w + b1v.w);
      *(float4*)(sU + ((nG<<1)+j)*64 + d0) = v;
    }
    __syncthreads();
    // stage 2: warp handles 4 nodes; lane covers k = lane, lane+32
    #pragma unroll
    for (int j = 0; j < 4; j++){
      const int nl = (warp<<2) + j;
      const float u0 = sU[nl*64 + lane];
      const float u1 = sU[nl*64 + lane + 32];
      float o0 = u0*sW2[lane*2]   + u1*sW2[(lane+32)*2];
      float o1 = u0*sW2[lane*2+1] + u1*sW2[(lane+32)*2+1];
      #pragma unroll
      for (int o = 16; o; o >>= 1){
        o0 += __shfl_xor_sync(0xffffffffu, o0, o);
        o1 += __shfl_xor_sync(0xffffffffu, o1, o);
      }
      if (lane == 0){
        out[(size_t)(node0 + nl)*2]     = o0 + sW2[128];
        out[(size_t)(node0 + nl)*2 + 1] = o1 + sW2[129];
      }
    }
    __syncthreads();
  }
}

// ---------------- host -------------------------------------------------------
extern "C" void kernel_launch(void* const* d_in, const int* in_sizes, int n_in,
                              void* d_out, int out_size){
  const float* x      = (const float*)d_in[0];
  const float* ea     = (const float*)d_in[1];
  const int*   ei     = (const int*)  d_in[2];
  const float* enc_W  = (const float*)d_in[3];
  const float* enc_b  = (const float*)d_in[4];
  const float* msg_W1 = (const float*)d_in[5];
  const float* msg_b1 = (const float*)d_in[6];
  const float* msg_lg = (const float*)d_in[7];
  const float* msg_lb = (const float*)d_in[8];
  const float* msg_W2 = (const float*)d_in[9];
  const float* msg_b2 = (const float*)d_in[10];
  const float* up_W   = (const float*)d_in[11];
  const float* up_b   = (const float*)d_in[12];
  const float* up_lg  = (const float*)d_in[13];
  const float* up_lb  = (const float*)d_in[14];
  const float* gc_Wa  = (const float*)d_in[15];
  const float* gc_ba  = (const float*)d_in[16];
  const float* gc_Wb  = (const float*)d_in[17];
  const float* gc_bb  = (const float*)d_in[18];
  const float* gc_Wc  = (const float*)d_in[19];
  const float* gc_bc  = (const float*)d_in[20];
  const float* dec_W1 = (const float*)d_in[21];
  const float* dec_b1 = (const float*)d_in[22];
  const float* dec_W2 = (const float*)d_in[23];
  const float* dec_b2 = (const float*)d_in[24];
  float* out = (float*)d_out;

  void *p_h, *p_P, *p_Q, *p_aggr, *p_gs, *p_deg;
  cudaGetSymbolAddress(&p_h, g_h);
  cudaGetSymbolAddress(&p_P, g_P);
  cudaGetSymbolAddress(&p_Q, g_Q);
  cudaGetSymbolAddress(&p_aggr, g_aggr);
  cudaGetSymbolAddress(&p_gs, g_gs);
  cudaGetSymbolAddress(&p_deg, g_deg);

  const int SM_PQ  = (2*DD*WPAD + TILE*DD) * 4;              // 151552
  const int SM_W2  = (DD*WPAD + TILE*DD) * 4;                //  83968
  const int SM_UP  = (256*WPAD + TILE*256 + TILE*DD) * 4;    // 184320
  const int SM_GC  = (2*DD*WPAD + 2*TILE*DD) * 4;            // 167936
  const int SM_DEC = (DD*68 + TILE*DD + TILE*64 + 130) * 4;  //  ~60KB
  cudaFuncSetAttribute(k_gemmPQ, cudaFuncAttributeMaxDynamicSharedMemorySize, SM_PQ);
  cudaFuncSetAttribute(k_gemmW2, cudaFuncAttributeMaxDynamicSharedMemorySize, SM_W2);
  cudaFuncSetAttribute(k_update, cudaFuncAttributeMaxDynamicSharedMemorySize, SM_UP);
  cudaFuncSetAttribute(k_gc,     cudaFuncAttributeMaxDynamicSharedMemorySize, SM_GC);
  cudaFuncSetAttribute(k_dec,    cudaFuncAttributeMaxDynamicSharedMemorySize, SM_DEC);

  cudaMemsetAsync(p_deg, 0, NN*sizeof(int), 0);
  k_encoder<<<BN, DD>>>(x, enc_W, enc_b);
  k_deg<<<(EE + 255)/256, 256>>>(ei);
  k_scan<<<1, 1024>>>();
  k_scatter<<<(EE + 255)/256, 256>>>(ei, ea);

  for (int l = 0; l < NLAYERS; l++){
    const float* W1  = msg_W1 + (size_t)l*258*DD;
    const float* W1a = W1;
    const float* W1b = W1 + 128*DD;
    const float* W1c = W1 + 256*DD;
    const float* b1  = msg_b1 + l*DD;
    const float* mlg = msg_lg + l*DD;
    const float* mlb = msg_lb + l*DD;
    const float* W2  = msg_W2 + (size_t)l*DD*DD;
    const float* b2  = msg_b2 + l*DD;
    const float* uWl = up_W  + (size_t)l*256*DD;
    const float* ubl = up_b  + l*DD;
    const float* ulg = up_lg + l*DD;
    const float* ulb = up_lb + l*DD;
    const float* Wa  = gc_Wa + (size_t)l*DD*DD;
    const float* ba  = gc_ba + l*DD;
    const float* Wb  = gc_Wb + (size_t)l*DD*DD;
    const float* bbv = gc_bb + l*DD;
    const float* Wc  = gc_Wc + (size_t)l*DD*DD;
    const float* bc  = gc_bc + l*DD;

    cudaMemsetAsync(p_gs, 0, BB*DD*sizeof(float), 0);

    k_gemmPQ<<<148, 256, SM_PQ>>>((const float*)p_h, W1a, W1b, (float*)p_P, (float*)p_Q);
    k_aggregate<<<(BB*NN)/8, 256>>>((const float*)p_P, (const float*)p_Q,
                                    W1c, b1, mlg, mlb, (float*)p_aggr);
    k_gemmW2<<<148, 256, SM_W2>>>((const float*)p_aggr, W2, b2, (float*)p_P);
    k_update<<<148, 256, SM_UP>>>((const float*)p_P, uWl, ubl, ulg, ulb);
    k_gc<<<148, 256, SM_GC>>>((const float*)p_h, Wa, ba, Wb);
    k_gate<<<BB, DD>>>(Wc, bc, bbv);
    k_scale<<<(BN*DD + 255)/256, 256>>>();
  }

  k_dec<<<148, 256, SM_DEC>>>(dec_W1, dec_b1, dec_W2, dec_b2, out);
}

// round 6
// speedup vs baseline: 2.0856x; 1.3690x over previous
#include <cuda_runtime.h>
#include <math.h>

#define BB 2
#define NN 10000
#define EE 160000
#define DD 128
#define DIN 5
#define NLAYERS 4
#define BN (BB*NN)
#define NEGS 0.2f
#define EPSF 1e-5f
#define TILE 32
#define WPAD 132   // padded W row stride (floats)

// ---------------- scratch (device globals) -----------------------------------
__device__ float g_h[BN*DD];
__device__ float g_P[BN*DD];
__device__ float g_Q[BN*DD];
__device__ float g_aggr[BN*DD];
__device__ int   g_deg[NN];
__device__ int   g_row_off[NN+1];
__device__ int   g_cur[NN];
__device__ int   g_csr_col[EE];
__device__ float2 g_csr_ea[EE];
__device__ float g_gs[BB*DD];
__device__ float g_gate[BB*DD];
__device__ float g_W2u[NLAYERS*DD*DD];   // W2 @ uW_bot
__device__ float g_b2u[NLAYERS*DD];      // b2 @ uW_bot

__device__ __forceinline__ float lrelu(float x){ return x > 0.f ? x : NEGS*x; }

__device__ __forceinline__ void fma4(float4& acc, const float4 x,
                                     const float4 w0, const float4 w1,
                                     const float4 w2, const float4 w3){
  acc.x += x.x*w0.x + x.y*w1.x + x.z*w2.x + x.w*w3.x;
  acc.y += x.x*w0.y + x.y*w1.y + x.z*w2.y + x.w*w3.y;
  acc.z += x.x*w0.z + x.y*w1.z + x.z*w2.z + x.w*w3.z;
  acc.w += x.x*w0.w + x.y*w1.w + x.z*w2.w + x.w*w3.w;
}

// ---------------- encoder ----------------------------------------------------
__global__ void k_encoder(const float* __restrict__ x, const float* __restrict__ W,
                          const float* __restrict__ b){
  int bn = blockIdx.x; int d = threadIdx.x;
  float acc = b[d];
  #pragma unroll
  for (int i = 0; i < DIN; i++) acc += x[bn*DIN + i] * W[i*DD + d];
  g_h[(size_t)bn*DD + d] = acc;
}

// ---------------- CSR build --------------------------------------------------
__global__ void k_deg(const int* __restrict__ ei){
  int e = blockIdx.x*blockDim.x + threadIdx.x;
  if (e < EE) atomicAdd(&g_deg[ei[e]], 1);
}

__global__ void k_scan(){   // 1 block, 1024 threads
  __shared__ int ssum[1024];
  const int t = threadIdx.x;
  const int base = t*10;
  int local[10];
  int s = 0;
  #pragma unroll
  for (int j = 0; j < 10; j++){
    int idx = base + j;
    int v = (idx < NN) ? g_deg[idx] : 0;
    local[j] = s; s += v;
  }
  ssum[t] = s;
  __syncthreads();
  for (int o = 1; o < 1024; o <<= 1){
    int v = (t >= o) ? ssum[t-o] : 0;
    __syncthreads();
    ssum[t] += v;
    __syncthreads();
  }
  int prefix = t ? ssum[t-1] : 0;
  #pragma unroll
  for (int j = 0; j < 10; j++){
    int idx = base + j;
    if (idx < NN){ g_row_off[idx] = prefix + local[j]; g_cur[idx] = prefix + local[j]; }
  }
  if (t == 0) g_row_off[NN] = EE;
}

__global__ void k_scatter(const int* __restrict__ ei, const float* __restrict__ ea){
  int e = blockIdx.x*blockDim.x + threadIdx.x;
  if (e >= EE) return;
  int r = ei[e];
  int pos = atomicAdd(&g_cur[r], 1);
  g_csr_col[pos] = ei[EE + e];
  g_csr_ea[pos] = make_float2(ea[2*e], ea[2*e+1]);
}

// ---------------- precompute W2u = W2 @ uW_bot, b2u = b2 @ uW_bot ------------
__global__ void k_prew2(const float* __restrict__ W2, const float* __restrict__ b2,
                        const float* __restrict__ uW){
  const int l = blockIdx.x, i = blockIdx.y, d = threadIdx.x;
  __shared__ float srow[DD];
  if (i < DD) srow[d] = W2[(size_t)l*DD*DD + i*DD + d];
  else        srow[d] = b2[l*DD + d];
  __syncthreads();
  const float* ub = uW + (size_t)l*256*DD + (size_t)DD*DD;   // bottom half rows
  float acc = 0.f;
  #pragma unroll 8
  for (int k = 0; k < DD; k++) acc += srow[k] * ub[k*DD + d];
  if (i < DD) g_W2u[(size_t)l*DD*DD + i*DD + d] = acc;
  else        g_b2u[l*DD + d] = acc;
}

// ---------------- dual GEMM: P = h@WA, Q = h@WB  (256 thr, TILE=32) ----------
__global__ __launch_bounds__(256,1) void k_gemmPQ(const float* __restrict__ h,
    const float* __restrict__ WA, const float* __restrict__ WB,
    float* __restrict__ P, float* __restrict__ Q){
  extern __shared__ float sm[];
  float* sWA = sm;                 // 128*132
  float* sWB = sm + DD*WPAD;       // 128*132
  float* sIn = sWB + DD*WPAD;      // 32*128
  const int t = threadIdx.x;
  const int dG = t & 31, nG = t >> 5;
  const int d0 = dG << 2;
  for (int i = t; i < DD*DD; i += 256){
    int k = i >> 7, d = i & 127;
    sWA[k*WPAD + d] = WA[i];
    sWB[k*WPAD + d] = WB[i];
  }
  __syncthreads();
  for (int tile = blockIdx.x; tile < BN/TILE; tile += gridDim.x){
    const int node0 = tile * TILE;
    { const float4* src = (const float4*)(h + (size_t)node0*DD);
      float4* dst = (float4*)sIn;
      for (int i = t; i < TILE*DD/4; i += 256) dst[i] = src[i]; }
    __syncthreads();
    float4 accA[4], accB[4];
    #pragma unroll
    for (int j = 0; j < 4; j++){ accA[j] = make_float4(0,0,0,0); accB[j] = make_float4(0,0,0,0); }
    #pragma unroll 4
    for (int k = 0; k < DD; k += 4){
      const float4 a0 = *(const float4*)(sWA + (k+0)*WPAD + d0);
      const float4 a1 = *(const float4*)(sWA + (k+1)*WPAD + d0);
      const float4 a2 = *(const float4*)(sWA + (k+2)*WPAD + d0);
      const float4 a3 = *(const float4*)(sWA + (k+3)*WPAD + d0);
      const float4 b0 = *(const float4*)(sWB + (k+0)*WPAD + d0);
      const float4 b1 = *(const float4*)(sWB + (k+1)*WPAD + d0);
      const float4 b2 = *(const float4*)(sWB + (k+2)*WPAD + d0);
      const float4 b3 = *(const float4*)(sWB + (k+3)*WPAD + d0);
      #pragma unroll
      for (int j = 0; j < 4; j++){
        const float4 x = *(const float4*)(sIn + ((nG<<2)+j)*DD + k);
        fma4(accA[j], x, a0, a1, a2, a3);
        fma4(accB[j], x, b0, b1, b2, b3);
      }
    }
    #pragma unroll
    for (int j = 0; j < 4; j++){
      const int node = node0 + (nG<<2) + j;
      *(float4*)(P + (size_t)node*DD + d0) = accA[j];
      *(float4*)(Q + (size_t)node*DD + d0) = accB[j];
    }
    __syncthreads();
  }
}

// ---------------- CSR aggregation (no atomics) -------------------------------
__global__ void k_aggregate(const float* __restrict__ P, const float* __restrict__ Q,
                            const float* __restrict__ W1c, const float* __restrict__ b1,
                            const float* __restrict__ lg, const float* __restrict__ lb,
                            float* __restrict__ aggr){
  const int w = (blockIdx.x*blockDim.x + threadIdx.x) >> 5;
  if (w >= BB*NN) return;
  const int lane = threadIdx.x & 31;
  const int b = w / NN, n = w - b*NN;
  const int off = g_row_off[n], end = g_row_off[n+1];
  const int bN = b*NN;
  const float4* Qv = (const float4*)Q;
  const float4 p  = ((const float4*)(P + (size_t)(bN + n)*DD))[lane];
  const float4 w0 = ((const float4*)W1c)[lane];
  const float4 w1 = ((const float4*)(W1c + DD))[lane];
  const float4 bv = ((const float4*)b1)[lane];
  const float4 gv = ((const float4*)lg)[lane];
  const float4 bt = ((const float4*)lb)[lane];
  float4 acc = make_float4(0,0,0,0);
  int ncol = 0; float2 nea = make_float2(0,0); float4 q = make_float4(0,0,0,0);
  if (off < end){
    ncol = g_csr_col[off]; nea = g_csr_ea[off];
    q = Qv[(size_t)(bN + ncol)*32 + lane];
  }
  for (int i = off; i < end; i++){
    const float4 qc = q; const float2 ec = nea;
    if (i + 1 < end){
      ncol = g_csr_col[i+1]; nea = g_csr_ea[i+1];
      q = Qv[(size_t)(bN + ncol)*32 + lane];
    }
    const float t0 = lrelu(p.x + qc.x + ec.x*w0.x + ec.y*w1.x + bv.x);
    const float t1 = lrelu(p.y + qc.y + ec.x*w0.y + ec.y*w1.y + bv.y);
    const float t2 = lrelu(p.z + qc.z + ec.x*w0.z + ec.y*w1.z + bv.z);
    const float t3 = lrelu(p.w + qc.w + ec.x*w0.w + ec.y*w1.w + bv.w);
    float s  = t0 + t1 + t2 + t3;
    float sq = t0*t0 + t1*t1 + t2*t2 + t3*t3;
    #pragma unroll
    for (int o = 16; o; o >>= 1){
      s  += __shfl_xor_sync(0xffffffffu, s,  o);
      sq += __shfl_xor_sync(0xffffffffu, sq, o);
    }
    const float mu = s * (1.f/DD);
    const float rs = rsqrtf(sq*(1.f/DD) - mu*mu + EPSF);
    acc.x += (t0 - mu)*rs*gv.x + bt.x;
    acc.y += (t1 - mu)*rs*gv.y + bt.y;
    acc.z += (t2 - mu)*rs*gv.z + bt.z;
    acc.w += (t3 - mu)*rs*gv.w + bt.w;
  }
  ((float4*)(aggr + (size_t)(bN + n)*DD))[lane] = acc;
}

// ---- node update: h += LN(lrelu(h@uW_t + aggr@W2u + deg*b2u + ub)) ----------
__global__ __launch_bounds__(256,1) void k_update(const float* __restrict__ aggr,
    const float* __restrict__ uW, const float* __restrict__ W2u,
    const float* __restrict__ b2u, const float* __restrict__ ub,
    const float* __restrict__ lg, const float* __restrict__ lb){
  extern __shared__ float sm[];
  float* sW  = sm;               // 256*132
  float* sIn = sm + 256*WPAD;    // 32*256
  const int t = threadIdx.x;
  const int dG = t & 31, nG = t >> 5;
  const int d0 = dG << 2;
  for (int i = t; i < 256*DD; i += 256){
    const int k = i >> 7, d = i & 127;
    sW[k*WPAD + d] = (k < DD) ? uW[i] : W2u[(k - DD)*DD + d];
  }
  const float4 ubv  = ((const float4*)ub)[dG];
  const float4 b2uv = ((const float4*)b2u)[dG];
  const float4 gvv  = ((const float4*)lg)[dG];
  const float4 bvv  = ((const float4*)lb)[dG];
  __syncthreads();
  const float4* h4 = (const float4*)g_h;
  const float4* a4 = (const float4*)aggr;
  for (int tile = blockIdx.x; tile < BN/TILE; tile += gridDim.x){
    const int node0 = tile * TILE;
    for (int i = t; i < TILE*DD/4; i += 256){
      const int nl = i >> 5, k4 = i & 31;
      const int node = node0 + nl;
      ((float4*)(sIn + nl*256))[k4]      = h4[(size_t)node*32 + k4];
      ((float4*)(sIn + nl*256 + DD))[k4] = a4[(size_t)node*32 + k4];
    }
    __syncthreads();
    float4 acc[4];
    #pragma unroll
    for (int j = 0; j < 4; j++) acc[j] = make_float4(0,0,0,0);
    #pragma unroll 4
    for (int k = 0; k < 256; k += 4){
      const float4 w0 = *(const float4*)(sW + (k+0)*WPAD + d0);
      const float4 w1 = *(const float4*)(sW + (k+1)*WPAD + d0);
      const float4 w2 = *(const float4*)(sW + (k+2)*WPAD + d0);
      const float4 w3 = *(const float4*)(sW + (k+3)*WPAD + d0);
      #pragma unroll
      for (int j = 0; j < 4; j++){
        const float4 x = *(const float4*)(sIn + ((nG<<2)+j)*256 + k);
        fma4(acc[j], x, w0, w1, w2, w3);
      }
    }
    #pragma unroll
    for (int j = 0; j < 4; j++){
      const int node = node0 + (nG<<2) + j;
      const float dg = (float)g_deg[node % NN];
      float4 v = acc[j];
      v.x = lrelu(v.x + ubv.x + dg*b2uv.x);
      v.y = lrelu(v.y + ubv.y + dg*b2uv.y);
      v.z = lrelu(v.z + ubv.z + dg*b2uv.z);
      v.w = lrelu(v.w + ubv.w + dg*b2uv.w);
      float s  = v.x + v.y + v.z + v.w;
      float sq = v.x*v.x + v.y*v.y + v.z*v.z + v.w*v.w;
      #pragma unroll
      for (int o = 16; o; o >>= 1){
        s  += __shfl_xor_sync(0xffffffffu, s,  o);
        sq += __shfl_xor_sync(0xffffffffu, sq, o);
      }
      const float mu = s * (1.f/DD);
      const float rs = rsqrtf(sq*(1.f/DD) - mu*mu + EPSF);
      const float4 hv = *(const float4*)(sIn + ((nG<<2)+j)*256 + d0);
      float4 o4;
      o4.x = hv.x + (v.x - mu)*rs*gvv.x + bvv.x;
      o4.y = hv.y + (v.y - mu)*rs*gvv.y + bvv.y;
      o4.z = hv.z + (v.z - mu)*rs*gvv.z + bvv.z;
      o4.w = hv.w + (v.w - mu)*rs*gvv.w + bvv.w;
      *(float4*)(g_h + (size_t)node*DD + d0) = o4;
    }
    __syncthreads();
  }
}

// ---------------- gc: g_gs[b] += sum_n lrelu(h@Wa + ba) ----------------------
__global__ __launch_bounds__(256,1) void k_gc(const float* __restrict__ h,
    const float* __restrict__ Wa, const float* __restrict__ ba){
  extern __shared__ float sm[];
  float* sWa  = sm;                // 128*132
  float* sIn  = sm + DD*WPAD;      // 32*128
  float* sRed = sIn + TILE*DD;     // 8*128
  const int t = threadIdx.x;
  const int dG = t & 31, nG = t >> 5;
  const int d0 = dG << 2;
  for (int i = t; i < DD*DD; i += 256){
    int k = i >> 7, d = i & 127;
    sWa[k*WPAD + d] = Wa[i];
  }
  const float4 bav = ((const float4*)ba)[dG];
  __syncthreads();
  float4 gs0 = make_float4(0,0,0,0), gs1 = make_float4(0,0,0,0);
  for (int tile = blockIdx.x; tile < BN/TILE; tile += gridDim.x){
    const int node0 = tile * TILE;
    { const float4* src = (const float4*)(h + (size_t)node0*DD);
      float4* dst = (float4*)sIn;
      for (int i = t; i < TILE*DD/4; i += 256) dst[i] = src[i]; }
    __syncthreads();
    float4 acc[4];
    #pragma unroll
    for (int j = 0; j < 4; j++) acc[j] = make_float4(0,0,0,0);
    #pragma unroll 4
    for (int k = 0; k < DD; k += 4){
      const float4 w0 = *(const float4*)(sWa + (k+0)*WPAD + d0);
      const float4 w1 = *(const float4*)(sWa + (k+1)*WPAD + d0);
      const float4 w2 = *(const float4*)(sWa + (k+2)*WPAD + d0);
      const float4 w3 = *(const float4*)(sWa + (k+3)*WPAD + d0);
      #pragma unroll
      for (int j = 0; j < 4; j++){
        const float4 x = *(const float4*)(sIn + ((nG<<2)+j)*DD + k);
        fma4(acc[j], x, w0, w1, w2, w3);
      }
    }
    #pragma unroll
    for (int j = 0; j < 4; j++){
      const int node = node0 + (nG<<2) + j;
      float4 v = acc[j];
      v.x = lrelu(v.x + bav.x); v.y = lrelu(v.y + bav.y);
      v.z = lrelu(v.z + bav.z); v.w = lrelu(v.w + bav.w);
      if (node < NN){ gs0.x += v.x; gs0.y += v.y; gs0.z += v.z; gs0.w += v.w; }
      else          { gs1.x += v.x; gs1.y += v.y; gs1.z += v.z; gs1.w += v.w; }
    }
    __syncthreads();
  }
  // block reduction: batch 0 then batch 1
  *(float4*)(sRed + nG*DD + d0) = gs0;
  __syncthreads();
  if (t < 32){
    float4 s = make_float4(0,0,0,0);
    #pragma unroll
    for (int r = 0; r < 8; r++){
      const float4 v = *(const float4*)(sRed + r*DD + t*4);
      s.x += v.x; s.y += v.y; s.z += v.z; s.w += v.w;
    }
    atomicAdd(&g_gs[t*4+0], s.x); atomicAdd(&g_gs[t*4+1], s.y);
    atomicAdd(&g_gs[t*4+2], s.z); atomicAdd(&g_gs[t*4+3], s.w);
  }
  __syncthreads();
  *(float4*)(sRed + nG*DD + d0) = gs1;
  __syncthreads();
  if (t < 32){
    float4 s = make_float4(0,0,0,0);
    #pragma unroll
    for (int r = 0; r < 8; r++){
      const float4 v = *(const float4*)(sRed + r*DD + t*4);
      s.x += v.x; s.y += v.y; s.z += v.z; s.w += v.w;
    }
    atomicAdd(&g_gs[DD+t*4+0], s.x); atomicAdd(&g_gs[DD+t*4+1], s.y);
    atomicAdd(&g_gs[DD+t*4+2], s.z); atomicAdd(&g_gs[DD+t*4+3], s.w);
  }
}

// ------- gate = sigmoid(((gs/N)@Wb + bb) @ Wc + bc) --------------------------
__global__ void k_gate(const float* __restrict__ Wb, const float* __restrict__ bb,
                       const float* __restrict__ Wc, const float* __restrict__ bc){
  const int b = blockIdx.x, d = threadIdx.x;
  __shared__ float zm[DD];
  __shared__ float s[DD];
  zm[d] = g_gs[b*DD + d] * (1.f/NN);
  __syncthreads();
  float acc = bb[d];
  #pragma unroll 8
  for (int k = 0; k < DD; k++) acc += zm[k] * Wb[k*DD + d];
  s[d] = acc;
  __syncthreads();
  float acc2 = bc[d];
  #pragma unroll 8
  for (int k = 0; k < DD; k++) acc2 += s[k] * Wc[k*DD + d];
  g_gate[b*DD + d] = 1.f/(1.f + expf(-acc2));
}

__global__ void k_scale(){
  const int i = blockIdx.x*blockDim.x + threadIdx.x;
  if (i < BN*DD){
    const int b = i / (NN*DD);
    g_h[i] *= g_gate[b*DD + (i & (DD-1))];
  }
}

// ---------------- decoder (register-tiled, 256 thr, TILE 32) -----------------
__global__ __launch_bounds__(256,1) void k_dec(const float* __restrict__ W1,
    const float* __restrict__ b1, const float* __restrict__ W2,
    const float* __restrict__ b2, float* __restrict__ out){
  extern __shared__ float sm[];
  float* sW1 = sm;               // 128*68
  float* sIn = sm + DD*68;       // 32*128
  float* sU  = sIn + 32*DD;      // 32*64
  float* sW2 = sU + 32*64;       // 128 + 2
  const int t = threadIdx.x;
  const int dG = t & 15, nG = t >> 4;
  const int d0 = dG << 2;
  const int lane = t & 31, warp = t >> 5;
  for (int i = t; i < DD*64; i += 256){
    int k = i >> 6, d = i & 63;
    sW1[k*68 + d] = W1[i];
  }
  if (t < 128) sW2[t] = W2[t];
  if (t < 2) sW2[128 + t] = b2[t];
  const float4 b1v = ((const float4*)b1)[dG];
  __syncthreads();
  for (int tile = blockIdx.x; tile < BN/32; tile += gridDim.x){
    const int node0 = tile * 32;
    { const float4* src = (const float4*)(g_h + (size_t)node0*DD);
      float4* dst = (float4*)sIn;
      for (int i = t; i < 32*DD/4; i += 256) dst[i] = src[i]; }
    __syncthreads();
    float4 acc[2];
    acc[0] = make_float4(0,0,0,0); acc[1] = make_float4(0,0,0,0);
    #pragma unroll 4
    for (int k = 0; k < DD; k += 4){
      const float4 w0 = *(const float4*)(sW1 + (k+0)*68 + d0);
      const float4 w1 = *(const float4*)(sW1 + (k+1)*68 + d0);
      const float4 w2 = *(const float4*)(sW1 + (k+2)*68 + d0);
      const float4 w3 = *(const float4*)(sW1 + (k+3)*68 + d0);
      #pragma unroll
      for (int j = 0; j < 2; j++){
        const float4 x = *(const float4*)(sIn + ((nG<<1)+j)*DD + k);
        fma4(acc[j], x, w0, w1, w2, w3);
      }
    }
    #pragma unroll
    for (int j = 0; j < 2; j++){
      float4 v = acc[j];
      v.x = lrelu(v.x + b1v.x); v.y = lrelu(v.y + b1v.y);
      v.z = lrelu(v.z + b1v.z); v.w = lrelu(v.w + b1v.w);
      *(float4*)(sU + ((nG<<1)+j)*64 + d0) = v;
    }
    __syncthreads();
    #pragma unroll
    for (int j = 0; j < 4; j++){
      const int nl = (warp<<2) + j;
      const float u0 = sU[nl*64 + lane];
      const float u1 = sU[nl*64 + lane + 32];
      float o0 = u0*sW2[lane*2]   + u1*sW2[(lane+32)*2];
      float o1 = u0*sW2[lane*2+1] + u1*sW2[(lane+32)*2+1];
      #pragma unroll
      for (int o = 16; o; o >>= 1){
        o0 += __shfl_xor_sync(0xffffffffu, o0, o);
        o1 += __shfl_xor_sync(0xffffffffu, o1, o);
      }
      if (lane == 0){
        out[(size_t)(node0 + nl)*2]     = o0 + sW2[128];
        out[(size_t)(node0 + nl)*2 + 1] = o1 + sW2[129];
      }
    }
    __syncthreads();
  }
}

// ---------------- host -------------------------------------------------------
extern "C" void kernel_launch(void* const* d_in, const int* in_sizes, int n_in,
                              void* d_out, int out_size){
  const float* x      = (const float*)d_in[0];
  const float* ea     = (const float*)d_in[1];
  const int*   ei     = (const int*)  d_in[2];
  const float* enc_W  = (const float*)d_in[3];
  const float* enc_b  = (const float*)d_in[4];
  const float* msg_W1 = (const float*)d_in[5];
  const float* msg_b1 = (const float*)d_in[6];
  const float* msg_lg = (const float*)d_in[7];
  const float* msg_lb = (const float*)d_in[8];
  const float* msg_W2 = (const float*)d_in[9];
  const float* msg_b2 = (const float*)d_in[10];
  const float* up_W   = (const float*)d_in[11];
  const float* up_b   = (const float*)d_in[12];
  const float* up_lg  = (const float*)d_in[13];
  const float* up_lb  = (const float*)d_in[14];
  const float* gc_Wa  = (const float*)d_in[15];
  const float* gc_ba  = (const float*)d_in[16];
  const float* gc_Wb  = (const float*)d_in[17];
  const float* gc_bb  = (const float*)d_in[18];
  const float* gc_Wc  = (const float*)d_in[19];
  const float* gc_bc  = (const float*)d_in[20];
  const float* dec_W1 = (const float*)d_in[21];
  const float* dec_b1 = (const float*)d_in[22];
  const float* dec_W2 = (const float*)d_in[23];
  const float* dec_b2 = (const float*)d_in[24];
  float* out = (float*)d_out;

  void *p_h, *p_P, *p_Q, *p_aggr, *p_gs, *p_deg, *p_W2u, *p_b2u;
  cudaGetSymbolAddress(&p_h, g_h);
  cudaGetSymbolAddress(&p_P, g_P);
  cudaGetSymbolAddress(&p_Q, g_Q);
  cudaGetSymbolAddress(&p_aggr, g_aggr);
  cudaGetSymbolAddress(&p_gs, g_gs);
  cudaGetSymbolAddress(&p_deg, g_deg);
  cudaGetSymbolAddress(&p_W2u, g_W2u);
  cudaGetSymbolAddress(&p_b2u, g_b2u);

  const int SM_PQ  = (2*DD*WPAD + TILE*DD) * 4;              // 151552
  const int SM_UP  = (256*WPAD + TILE*256) * 4;              // 167936
  const int SM_GC  = (DD*WPAD + TILE*DD + 8*DD) * 4;         //  88064
  const int SM_DEC = (DD*68 + 32*DD + 32*64 + 130) * 4;      //  59912
  cudaFuncSetAttribute(k_gemmPQ, cudaFuncAttributeMaxDynamicSharedMemorySize, SM_PQ);
  cudaFuncSetAttribute(k_update, cudaFuncAttributeMaxDynamicSharedMemorySize, SM_UP);
  cudaFuncSetAttribute(k_gc,     cudaFuncAttributeMaxDynamicSharedMemorySize, SM_GC);
  cudaFuncSetAttribute(k_dec,    cudaFuncAttributeMaxDynamicSharedMemorySize, SM_DEC);

  cudaMemsetAsync(p_deg, 0, NN*sizeof(int), 0);
  k_encoder<<<BN, DD>>>(x, enc_W, enc_b);
  k_deg<<<(EE + 255)/256, 256>>>(ei);
  k_scan<<<1, 1024>>>();
  k_scatter<<<(EE + 255)/256, 256>>>(ei, ea);
  { dim3 g(NLAYERS, DD+1); k_prew2<<<g, DD>>>(msg_W2, msg_b2, up_W); }

  for (int l = 0; l < NLAYERS; l++){
    const float* W1  = msg_W1 + (size_t)l*258*DD;
    const float* W1a = W1;
    const float* W1b = W1 + 128*DD;
    const float* W1c = W1 + 256*DD;
    const float* b1  = msg_b1 + l*DD;
    const float* mlg = msg_lg + l*DD;
    const float* mlb = msg_lb + l*DD;
    const float* uWl = up_W  + (size_t)l*256*DD;
    const float* ubl = up_b  + l*DD;
    const float* ulg = up_lg + l*DD;
    const float* ulb = up_lb + l*DD;
    const float* Wa  = gc_Wa + (size_t)l*DD*DD;
    const float* ba  = gc_ba + l*DD;
    const float* Wb  = gc_Wb + (size_t)l*DD*DD;
    const float* bbv = gc_bb + l*DD;
    const float* Wc  = gc_Wc + (size_t)l*DD*DD;
    const float* bc  = gc_bc + l*DD;
    const float* W2u = (const float*)p_W2u + (size_t)l*DD*DD;
    const float* b2u = (const float*)p_b2u + (size_t)l*DD;

    cudaMemsetAsync(p_gs, 0, BB*DD*sizeof(float), 0);

    k_gemmPQ<<<148, 256, SM_PQ>>>((const float*)p_h, W1a, W1b, (float*)p_P, (float*)p_Q);
    k_aggregate<<<(BB*NN)/8, 256>>>((const float*)p_P, (const float*)p_Q,
                                    W1c, b1, mlg, mlb, (float*)p_aggr);
    k_update<<<148, 256, SM_UP>>>((const float*)p_aggr, uWl, W2u, b2u, ubl, ulg, ulb);
    k_gc<<<148, 256, SM_GC>>>((const float*)p_h, Wa, ba);
    k_gate<<<BB, DD>>>(Wb, bbv, Wc, bc);
    k_scale<<<(BN*DD + 255)/256, 256>>>();
  }

  k_dec<<<148, 256, SM_DEC>>>(dec_W1, dec_b1, dec_W2, dec_b2, out);
}

// round 8
// speedup vs baseline: 2.3408x; 1.1224x over previous
#include <cuda_runtime.h>
#include <cuda_bf16.h>
#include <math.h>
#include <stdint.h>

#define BB 2
#define NN 10000
#define EE 160000
#define DD 128
#define DIN 5
#define NLAYERS 4
#define BN (BB*NN)
#define NEGS 0.2f
#define EPSF 1e-5f
#define TILE 32
#define WPAD 132
#define TM 128
#define NT_TILES ((BN + TM - 1) / TM)   // 157
#define SPAD 136                         // bf16 elems per padded smem row (272B)

// ---------------- scratch (device globals) -----------------------------------
__device__ float g_h[BN*DD];
__device__ float g_P[BN*DD];
__device__ float g_Q[BN*DD];
__device__ float g_aggr[BN*DD];
__device__ int   g_deg[NN];
__device__ int   g_row_off[NN+1];
__device__ int   g_cur[NN];
__device__ int   g_csr_col[EE];
__device__ float2 g_csr_ea[EE];
__device__ float g_gs[BB*DD];
__device__ float g_gate[BB*DD];
__device__ float g_W2u[NLAYERS*DD*DD];
__device__ float g_b2u[NLAYERS*DD];

__device__ __forceinline__ float lrelu(float x){ return x > 0.f ? x : NEGS*x; }

__device__ __forceinline__ uint32_t smem_u32(const void* p){
  uint32_t a;
  asm("{ .reg .u64 t; cvta.to.shared.u64 t, %1; cvt.u32.u64 %0, t; }" : "=r"(a) : "l"(p));
  return a;
}
__device__ __forceinline__ void bsplit(float x, __nv_bfloat16& h, __nv_bfloat16& l){
  h = __float2bfloat16(x);
  l = __float2bfloat16(x - __bfloat162float(h));
}
#define LDSM4(r0,r1,r2,r3,addr) \
  asm volatile("ldmatrix.sync.aligned.m8n8.x4.shared.b16 {%0,%1,%2,%3}, [%4];" \
    : "=r"(r0), "=r"(r1), "=r"(r2), "=r"(r3) : "r"(addr))
#define MMA16816(d, a0,a1,a2,a3, b0,b1) \
  asm volatile("mma.sync.aligned.m16n8k16.row.col.f32.bf16.bf16.f32 " \
    "{%0,%1,%2,%3}, {%4,%5,%6,%7}, {%8,%9}, {%0,%1,%2,%3};" \
    : "+f"((d)[0]), "+f"((d)[1]), "+f"((d)[2]), "+f"((d)[3]) \
    : "r"(a0), "r"(a1), "r"(a2), "r"(a3), "r"(b0), "r"(b1))

// ---------------- encoder ----------------------------------------------------
__global__ void k_encoder(const float* __restrict__ x, const float* __restrict__ W,
                          const float* __restrict__ b){
  int bn = blockIdx.x; int d = threadIdx.x;
  float acc = b[d];
  #pragma unroll
  for (int i = 0; i < DIN; i++) acc += x[bn*DIN + i] * W[i*DD + d];
  g_h[(size_t)bn*DD + d] = acc;
}

// ---------------- CSR build --------------------------------------------------
__global__ void k_deg(const int* __restrict__ ei){
  int e = blockIdx.x*blockDim.x + threadIdx.x;
  if (e < EE) atomicAdd(&g_deg[ei[e]], 1);
}

__global__ void k_scan(){
  __shared__ int ssum[1024];
  const int t = threadIdx.x;
  const int base = t*10;
  int local[10];
  int s = 0;
  #pragma unroll
  for (int j = 0; j < 10; j++){
    int idx = base + j;
    int v = (idx < NN) ? g_deg[idx] : 0;
    local[j] = s; s += v;
  }
  ssum[t] = s;
  __syncthreads();
  for (int o = 1; o < 1024; o <<= 1){
    int v = (t >= o) ? ssum[t-o] : 0;
    __syncthreads();
    ssum[t] += v;
    __syncthreads();
  }
  int prefix = t ? ssum[t-1] : 0;
  #pragma unroll
  for (int j = 0; j < 10; j++){
    int idx = base + j;
    if (idx < NN){ g_row_off[idx] = prefix + local[j]; g_cur[idx] = prefix + local[j]; }
  }
  if (t == 0) g_row_off[NN] = EE;
}

__global__ void k_scatter(const int* __restrict__ ei, const float* __restrict__ ea){
  int e = blockIdx.x*blockDim.x + threadIdx.x;
  if (e >= EE) return;
  int r = ei[e];
  int pos = atomicAdd(&g_cur[r], 1);
  g_csr_col[pos] = ei[EE + e];
  g_csr_ea[pos] = make_float2(ea[2*e], ea[2*e+1]);
}

// ---------------- precompute W2u = W2 @ uW_bot, b2u = b2 @ uW_bot ------------
__global__ void k_prew2(const float* __restrict__ W2, const float* __restrict__ b2,
                        const float* __restrict__ uW){
  const int l = blockIdx.x, i = blockIdx.y, d = threadIdx.x;
  __shared__ float srow[DD];
  if (i < DD) srow[d] = W2[(size_t)l*DD*DD + i*DD + d];
  else        srow[d] = b2[l*DD + d];
  __syncthreads();
  const float* ub = uW + (size_t)l*256*DD + (size_t)DD*DD;
  float acc = 0.f;
  #pragma unroll 8
  for (int k = 0; k < DD; k++) acc += srow[k] * ub[k*DD + d];
  if (i < DD) g_W2u[(size_t)l*DD*DD + i*DD + d] = acc;
  else        g_b2u[l*DD + d] = acc;
}

// ======== HMMA GEMM 1: P = h@WA, Q = h@WB ====================================
// smem: Ah, Al, Bah, Bal, Bbh, Bbl — each [128][SPAD] bf16
__global__ __launch_bounds__(256,1) void k_mmaPQ(
    const float* __restrict__ h, const float* __restrict__ WA,
    const float* __restrict__ WB, float* __restrict__ P, float* __restrict__ Q){
  extern __shared__ __nv_bfloat16 sm_[];
  __nv_bfloat16* Ah  = sm_;
  __nv_bfloat16* Al  = Ah  + 128*SPAD;
  __nv_bfloat16* Bah = Al  + 128*SPAD;
  __nv_bfloat16* Bal = Bah + 128*SPAD;
  __nv_bfloat16* Bbh = Bal + 128*SPAD;
  __nv_bfloat16* Bbl = Bbh + 128*SPAD;
  const int t = threadIdx.x, w = t >> 5, l = t & 31;
  // stage both weights transposed: B[n][k] = W[k][n]
  for (int idx = t; idx < DD*DD; idx += 256){
    int k = idx >> 7, n = idx & 127;
    __nv_bfloat16 hh, ll;
    bsplit(WA[idx], hh, ll);
    Bah[n*SPAD + k] = hh; Bal[n*SPAD + k] = ll;
    bsplit(WB[idx], hh, ll);
    Bbh[n*SPAD + k] = hh; Bbl[n*SPAD + k] = ll;
  }
  __syncthreads();
  const int m0 = w * 16;
  const int arow = (l & 7) + ((l >> 3) & 1)*8, acol = ((l >> 4) & 1)*8;
  const int brow = (l & 7) + ((l >> 4) & 1)*8, bcol = ((l >> 3) & 1)*8;
  const uint32_t uAh = smem_u32(Ah) + ((m0 + arow)*SPAD + acol)*2;
  const uint32_t uAl = smem_u32(Al) + ((m0 + arow)*SPAD + acol)*2;
  const uint32_t uB[2][2] = {
    { smem_u32(Bah) + (brow*SPAD + bcol)*2, smem_u32(Bal) + (brow*SPAD + bcol)*2 },
    { smem_u32(Bbh) + (brow*SPAD + bcol)*2, smem_u32(Bbl) + (brow*SPAD + bcol)*2 } };
  for (int tile = blockIdx.x; tile < NT_TILES; tile += gridDim.x){
    const int node0 = tile * TM;
    for (int idx = t; idx < TM*64; idx += 256){
      int r = idx >> 6, k2 = (idx & 63) * 2;
      int node = node0 + r;
      float2 x = (node < BN) ? *(const float2*)(h + (size_t)node*DD + k2)
                             : make_float2(0.f, 0.f);
      __nv_bfloat16 h0,l0,h1,l1;
      bsplit(x.x, h0, l0); bsplit(x.y, h1, l1);
      *(__nv_bfloat162*)(Ah + r*SPAD + k2) = __halves2bfloat162(h0, h1);
      *(__nv_bfloat162*)(Al + r*SPAD + k2) = __halves2bfloat162(l0, l1);
    }
    __syncthreads();
    #pragma unroll
    for (int out = 0; out < 2; out++){
      float acc[64];
      #pragma unroll
      for (int i = 0; i < 64; i++) acc[i] = 0.f;
      #pragma unroll
      for (int ks = 0; ks < 8; ks++){
        const uint32_t ko = ks * 32;   // 16 bf16 * 2B
        uint32_t a0,a1,a2,a3, e0,e1,e2,e3;
        LDSM4(a0,a1,a2,a3, uAh + ko);
        LDSM4(e0,e1,e2,e3, uAl + ko);
        #pragma unroll
        for (int nt2 = 0; nt2 < 8; nt2++){
          const uint32_t no = nt2 * (16*SPAD*2);
          uint32_t bh0,bh1,bh2,bh3, bl0,bl1,bl2,bl3;
          LDSM4(bh0,bh1,bh2,bh3, uB[out][0] + no + ko);
          LDSM4(bl0,bl1,bl2,bl3, uB[out][1] + no + ko);
          float* d0 = acc + (nt2*2+0)*4;
          float* d1 = acc + (nt2*2+1)*4;
          MMA16816(d0, a0,a1,a2,a3, bh0,bh1);
          MMA16816(d0, a0,a1,a2,a3, bl0,bl1);
          MMA16816(d0, e0,e1,e2,e3, bh0,bh1);
          MMA16816(d1, a0,a1,a2,a3, bh2,bh3);
          MMA16816(d1, a0,a1,a2,a3, bl2,bl3);
          MMA16816(d1, e0,e1,e2,e3, bh2,bh3);
        }
      }
      float* Out = out ? Q : P;
      const int r0 = m0 + (l >> 2);
      const int n0v = node0 + r0, n1v = n0v + 8;
      #pragma unroll
      for (int nt = 0; nt < 16; nt++){
        const int col = nt*8 + 2*(l & 3);
        if (n0v < BN) *(float2*)(Out + (size_t)n0v*DD + col) = make_float2(acc[nt*4+0], acc[nt*4+1]);
        if (n1v < BN) *(float2*)(Out + (size_t)n1v*DD + col) = make_float2(acc[nt*4+2], acc[nt*4+3]);
      }
    }
    __syncthreads();
  }
}

// ======== HMMA GEMM 2: h += LN(lrelu(h@uW_top + aggr@W2u + deg*b2u + ub)) ====
// smem: sVec[512]f32; A hi/lo [128][SPAD]; B0 hi/lo; B1 hi/lo
__global__ __launch_bounds__(256,1) void k_mmaUP(
    const float* __restrict__ aggr, const float* __restrict__ uW,
    const float* __restrict__ W2u, const float* __restrict__ b2u,
    const float* __restrict__ ub, const float* __restrict__ lg,
    const float* __restrict__ lb){
  extern __shared__ float smf_[];
  float* sVec = smf_;                      // ub, b2u, lg, lb
  __nv_bfloat16* Ah  = (__nv_bfloat16*)(smf_ + 512);
  __nv_bfloat16* Al  = Ah  + 128*SPAD;
  __nv_bfloat16* B0h = Al  + 128*SPAD;
  __nv_bfloat16* B0l = B0h + 128*SPAD;
  __nv_bfloat16* B1h = B0l + 128*SPAD;
  __nv_bfloat16* B1l = B1h + 128*SPAD;
  const int t = threadIdx.x, w = t >> 5, l = t & 31;
  if (t < 128){
    sVec[t] = ub[t]; sVec[128 + t] = b2u[t];
    sVec[256 + t] = lg[t]; sVec[384 + t] = lb[t];
  }
  for (int idx = t; idx < DD*DD; idx += 256){
    int k = idx >> 7, n = idx & 127;
    __nv_bfloat16 hh, ll;
    bsplit(uW[idx], hh, ll);          // top half rows of uW
    B0h[n*SPAD + k] = hh; B0l[n*SPAD + k] = ll;
    bsplit(W2u[idx], hh, ll);
    B1h[n*SPAD + k] = hh; B1l[n*SPAD + k] = ll;
  }
  __syncthreads();
  const int m0 = w * 16;
  const int arow = (l & 7) + ((l >> 3) & 1)*8, acol = ((l >> 4) & 1)*8;
  const int brow = (l & 7) + ((l >> 4) & 1)*8, bcol = ((l >> 3) & 1)*8;
  const uint32_t uAh = smem_u32(Ah) + ((m0 + arow)*SPAD + acol)*2;
  const uint32_t uAl = smem_u32(Al) + ((m0 + arow)*SPAD + acol)*2;
  const uint32_t uB[2][2] = {
    { smem_u32(B0h) + (brow*SPAD + bcol)*2, smem_u32(B0l) + (brow*SPAD + bcol)*2 },
    { smem_u32(B1h) + (brow*SPAD + bcol)*2, smem_u32(B1l) + (brow*SPAD + bcol)*2 } };
  for (int tile = blockIdx.x; tile < NT_TILES; tile += gridDim.x){
    const int node0 = tile * TM;
    float acc[64];
    #pragma unroll
    for (int i = 0; i < 64; i++) acc[i] = 0.f;
    #pragma unroll
    for (int chunk = 0; chunk < 2; chunk++){
      const float* src = chunk ? aggr : g_h;
      for (int idx = t; idx < TM*64; idx += 256){
        int r = idx >> 6, k2 = (idx & 63) * 2;
        int node = node0 + r;
        float2 x = (node < BN) ? *(const float2*)(src + (size_t)node*DD + k2)
                               : make_float2(0.f, 0.f);
        __nv_bfloat16 h0,l0,h1,l1;
        bsplit(x.x, h0, l0); bsplit(x.y, h1, l1);
        *(__nv_bfloat162*)(Ah + r*SPAD + k2) = __halves2bfloat162(h0, h1);
        *(__nv_bfloat162*)(Al + r*SPAD + k2) = __halves2bfloat162(l0, l1);
      }
      __syncthreads();
      #pragma unroll
      for (int ks = 0; ks < 8; ks++){
        const uint32_t ko = ks * 32;
        uint32_t a0,a1,a2,a3, e0,e1,e2,e3;
        LDSM4(a0,a1,a2,a3, uAh + ko);
        LDSM4(e0,e1,e2,e3, uAl + ko);
        #pragma unroll
        for (int nt2 = 0; nt2 < 8; nt2++){
          const uint32_t no = nt2 * (16*SPAD*2);
          uint32_t bh0,bh1,bh2,bh3, bl0,bl1,bl2,bl3;
          LDSM4(bh0,bh1,bh2,bh3, uB[chunk][0] + no + ko);
          LDSM4(bl0,bl1,bl2,bl3, uB[chunk][1] + no + ko);
          float* d0 = acc + (nt2*2+0)*4;
          float* d1 = acc + (nt2*2+1)*4;
          MMA16816(d0, a0,a1,a2,a3, bh0,bh1);
          MMA16816(d0, a0,a1,a2,a3, bl0,bl1);
          MMA16816(d0, e0,e1,e2,e3, bh0,bh1);
          MMA16816(d1, a0,a1,a2,a3, bh2,bh3);
          MMA16816(d1, a0,a1,a2,a3, bl2,bl3);
          MMA16816(d1, e0,e1,e2,e3, bh2,bh3);
        }
      }
      __syncthreads();  // A smem free before restage
    }
    // epilogue: lrelu + per-row LN (row in lane-quad) + residual into g_h
    const int r0 = m0 + (l >> 2);
    const int n0v = node0 + r0, n1v = n0v + 8;
    const float dg0 = (n0v < BN) ? (float)g_deg[n0v % NN] : 0.f;
    const float dg1 = (n1v < BN) ? (float)g_deg[n1v % NN] : 0.f;
    float s0 = 0.f, q0 = 0.f, s1 = 0.f, q1 = 0.f;
    #pragma unroll
    for (int nt = 0; nt < 16; nt++){
      const int col = nt*8 + 2*(l & 3);
      float v0 = lrelu(acc[nt*4+0] + sVec[col]   + dg0*sVec[128+col]);
      float v1 = lrelu(acc[nt*4+1] + sVec[col+1] + dg0*sVec[129+col]);
      float v2 = lrelu(acc[nt*4+2] + sVec[col]   + dg1*sVec[128+col]);
      float v3 = lrelu(acc[nt*4+3] + sVec[col+1] + dg1*sVec[129+col]);
      acc[nt*4+0] = v0; acc[nt*4+1] = v1; acc[nt*4+2] = v2; acc[nt*4+3] = v3;
      s0 += v0 + v1; q0 += v0*v0 + v1*v1;
      s1 += v2 + v3; q1 += v2*v2 + v3*v3;
    }
    #pragma unroll
    for (int o = 1; o < 4; o <<= 1){
      s0 += __shfl_xor_sync(0xffffffffu, s0, o);
      q0 += __shfl_xor_sync(0xffffffffu, q0, o);
      s1 += __shfl_xor_sync(0xffffffffu, s1, o);
      q1 += __shfl_xor_sync(0xffffffffu, q1, o);
    }
    const float mu0 = s0 * (1.f/DD);
    const float rs0 = rsqrtf(q0*(1.f/DD) - mu0*mu0 + EPSF);
    const float mu1 = s1 * (1.f/DD);
    const float rs1 = rsqrtf(q1*(1.f/DD) - mu1*mu1 + EPSF);
    #pragma unroll
    for (int nt = 0; nt < 16; nt++){
      const int col = nt*8 + 2*(l & 3);
      if (n0v < BN){
        float2 h2 = *(float2*)(g_h + (size_t)n0v*DD + col);
        h2.x += (acc[nt*4+0] - mu0)*rs0*sVec[256+col]   + sVec[384+col];
        h2.y += (acc[nt*4+1] - mu0)*rs0*sVec[257+col]   + sVec[385+col];
        *(float2*)(g_h + (size_t)n0v*DD + col) = h2;
      }
      if (n1v < BN){
        float2 h2 = *(float2*)(g_h + (size_t)n1v*DD + col);
        h2.x += (acc[nt*4+2] - mu1)*rs1*sVec[256+col]   + sVec[384+col];
        h2.y += (acc[nt*4+3] - mu1)*rs1*sVec[257+col]   + sVec[385+col];
        *(float2*)(g_h + (size_t)n1v*DD + col) = h2;
      }
    }
    __syncthreads();
  }
}

// ---------------- CSR aggregation (no atomics) -------------------------------
__global__ void k_aggregate(const float* __restrict__ P, const float* __restrict__ Q,
                            const float* __restrict__ W1c, const float* __restrict__ b1,
                            const float* __restrict__ lg, const float* __restrict__ lb,
                            float* __restrict__ aggr){
  const int w = (blockIdx.x*blockDim.x + threadIdx.x) >> 5;
  if (w >= BB*NN) return;
  const int lane = threadIdx.x & 31;
  const int b = w / NN, n = w - b*NN;
  const int off = g_row_off[n], end = g_row_off[n+1];
  const int bN = b*NN;
  const float4* Qv = (const float4*)Q;
  const float4 p  = ((const float4*)(P + (size_t)(bN + n)*DD))[lane];
  const float4 w0 = ((const float4*)W1c)[lane];
  const float4 w1 = ((const float4*)(W1c + DD))[lane];
  const float4 bv = ((const float4*)b1)[lane];
  const float4 gv = ((const float4*)lg)[lane];
  const float4 bt = ((const float4*)lb)[lane];
  float4 acc = make_float4(0,0,0,0);
  int ncol = 0; float2 nea = make_float2(0,0); float4 q = make_float4(0,0,0,0);
  if (off < end){
    ncol = g_csr_col[off]; nea = g_csr_ea[off];
    q = Qv[(size_t)(bN + ncol)*32 + lane];
  }
  for (int i = off; i < end; i++){
    const float4 qc = q; const float2 ec = nea;
    if (i + 1 < end){
      ncol = g_csr_col[i+1]; nea = g_csr_ea[i+1];
      q = Qv[(size_t)(bN + ncol)*32 + lane];
    }
    const float t0 = lrelu(p.x + qc.x + ec.x*w0.x + ec.y*w1.x + bv.x);
    const float t1 = lrelu(p.y + qc.y + ec.x*w0.y + ec.y*w1.y + bv.y);
    const float t2 = lrelu(p.z + qc.z + ec.x*w0.z + ec.y*w1.z + bv.z);
    const float t3 = lrelu(p.w + qc.w + ec.x*w0.w + ec.y*w1.w + bv.w);
    float s  = t0 + t1 + t2 + t3;
    float sq = t0*t0 + t1*t1 + t2*t2 + t3*t3;
    #pragma unroll
    for (int o = 16; o; o >>= 1){
      s  += __shfl_xor_sync(0xffffffffu, s,  o);
      sq += __shfl_xor_sync(0xffffffffu, sq, o);
    }
    const float mu = s * (1.f/DD);
    const float rs = rsqrtf(sq*(1.f/DD) - mu*mu + EPSF);
    acc.x += (t0 - mu)*rs*gv.x + bt.x;
    acc.y += (t1 - mu)*rs*gv.y + bt.y;
    acc.z += (t2 - mu)*rs*gv.z + bt.z;
    acc.w += (t3 - mu)*rs*gv.w + bt.w;
  }
  ((float4*)(aggr + (size_t)(bN + n)*DD))[lane] = acc;
}

__device__ __forceinline__ void fma4(float4& acc, const float4 x,
                                     const float4 w0, const float4 w1,
                                     const float4 w2, const float4 w3){
  acc.x += x.x*w0.x + x.y*w1.x + x.z*w2.x + x.w*w3.x;
  acc.y += x.x*w0.y + x.y*w1.y + x.z*w2.y + x.w*w3.y;
  acc.z += x.x*w0.z + x.y*w1.z + x.z*w2.z + x.w*w3.z;
  acc.w += x.x*w0.w + x.y*w1.w + x.z*w2.w + x.w*w3.w;
}

// ---------------- gc: g_gs[b] += sum_n lrelu(h@Wa + ba)  (FFMA) --------------
__global__ __launch_bounds__(256,1) void k_gc(const float* __restrict__ h,
    const float* __restrict__ Wa, const float* __restrict__ ba){
  extern __shared__ float sm[];
  float* sWa  = sm;
  float* sIn  = sm + DD*WPAD;
  float* sRed = sIn + TILE*DD;
  const int t = threadIdx.x;
  const int dG = t & 31, nG = t >> 5;
  const int d0 = dG << 2;
  for (int i = t; i < DD*DD; i += 256){
    int k = i >> 7, d = i & 127;
    sWa[k*WPAD + d] = Wa[i];
  }
  const float4 bav = ((const float4*)ba)[dG];
  __syncthreads();
  float4 gs0 = make_float4(0,0,0,0), gs1 = make_float4(0,0,0,0);
  for (int tile = blockIdx.x; tile < BN/TILE; tile += gridDim.x){
    const int node0 = tile * TILE;
    { const float4* src = (const float4*)(h + (size_t)node0*DD);
      float4* dst = (float4*)sIn;
      for (int i = t; i < TILE*DD/4; i += 256) dst[i] = src[i]; }
    __syncthreads();
    float4 acc[4];
    #pragma unroll
    for (int j = 0; j < 4; j++) acc[j] = make_float4(0,0,0,0);
    #pragma unroll 4
    for (int k = 0; k < DD; k += 4){
      const float4 w0 = *(const float4*)(sWa + (k+0)*WPAD + d0);
      const float4 w1 = *(const float4*)(sWa + (k+1)*WPAD + d0);
      const float4 w2 = *(const float4*)(sWa + (k+2)*WPAD + d0);
      const float4 w3 = *(const float4*)(sWa + (k+3)*WPAD + d0);
      #pragma unroll
      for (int j = 0; j < 4; j++){
        const float4 x = *(const float4*)(sIn + ((nG<<2)+j)*DD + k);
        fma4(acc[j], x, w0, w1, w2, w3);
      }
    }
    #pragma unroll
    for (int j = 0; j < 4; j++){
      const int node = node0 + (nG<<2) + j;
      float4 v = acc[j];
      v.x = lrelu(v.x + bav.x); v.y = lrelu(v.y + bav.y);
      v.z = lrelu(v.z + bav.z); v.w = lrelu(v.w + bav.w);
      if (node < NN){ gs0.x += v.x; gs0.y += v.y; gs0.z += v.z; gs0.w += v.w; }
      else          { gs1.x += v.x; gs1.y += v.y; gs1.z += v.z; gs1.w += v.w; }
    }
    __syncthreads();
  }
  *(float4*)(sRed + nG*DD + d0) = gs0;
  __syncthreads();
  if (t < 32){
    float4 s = make_float4(0,0,0,0);
    #pragma unroll
    for (int r = 0; r < 8; r++){
      const float4 v = *(const float4*)(sRed + r*DD + t*4);
      s.x += v.x; s.y += v.y; s.z += v.z; s.w += v.w;
    }
    atomicAdd(&g_gs[t*4+0], s.x); atomicAdd(&g_gs[t*4+1], s.y);
    atomicAdd(&g_gs[t*4+2], s.z); atomicAdd(&g_gs[t*4+3], s.w);
  }
  __syncthreads();
  *(float4*)(sRed + nG*DD + d0) = gs1;
  __syncthreads();
  if (t < 32){
    float4 s = make_float4(0,0,0,0);
    #pragma unroll
    for (int r = 0; r < 8; r++){
      const float4 v = *(const float4*)(sRed + r*DD + t*4);
      s.x += v.x; s.y += v.y; s.z += v.z; s.w += v.w;
    }
    atomicAdd(&g_gs[DD+t*4+0], s.x); atomicAdd(&g_gs[DD+t*4+1], s.y);
    atomicAdd(&g_gs[DD+t*4+2], s.z); atomicAdd(&g_gs[DD+t*4+3], s.w);
  }
}

// ------- gate = sigmoid(((gs/N)@Wb + bb) @ Wc + bc) --------------------------
__global__ void k_gate(const float* __restrict__ Wb, const float* __restrict__ bb,
                       const float* __restrict__ Wc, const float* __restrict__ bc){
  const int b = blockIdx.x, d = threadIdx.x;
  __shared__ float zm[DD];
  __shared__ float s[DD];
  zm[d] = g_gs[b*DD + d] * (1.f/NN);
  __syncthreads();
  float acc = bb[d];
  #pragma unroll 8
  for (int k = 0; k < DD; k++) acc += zm[k] * Wb[k*DD + d];
  s[d] = acc;
  __syncthreads();
  float acc2 = bc[d];
  #pragma unroll 8
  for (int k = 0; k < DD; k++) acc2 += s[k] * Wc[k*DD + d];
  g_gate[b*DD + d] = 1.f/(1.f + expf(-acc2));
}

__global__ void k_scale(){
  const int i = blockIdx.x*blockDim.x + threadIdx.x;
  if (i < BN*DD){
    const int b = i / (NN*DD);
    g_h[i] *= g_gate[b*DD + (i & (DD-1))];
  }
}

// ---------------- decoder ----------------------------------------------------
__global__ __launch_bounds__(256,1) void k_dec(const float* __restrict__ W1,
    const float* __restrict__ b1, const float* __restrict__ W2,
    const float* __restrict__ b2, float* __restrict__ out){
  extern __shared__ float sm[];
  float* sW1 = sm;
  float* sIn = sm + DD*68;
  float* sU  = sIn + 32*DD;
  float* sW2 = sU + 32*64;
  const int t = threadIdx.x;
  const int dG = t & 15, nG = t >> 4;
  const int d0 = dG << 2;
  const int lane = t & 31, warp = t >> 5;
  for (int i = t; i < DD*64; i += 256){
    int k = i >> 6, d = i & 63;
    sW1[k*68 + d] = W1[i];
  }
  if (t < 128) sW2[t] = W2[t];
  if (t < 2) sW2[128 + t] = b2[t];
  const float4 b1v = ((const float4*)b1)[dG];
  __syncthreads();
  for (int tile = blockIdx.x; tile < BN/32; tile += gridDim.x){
    const int node0 = tile * 32;
    { const float4* src = (const float4*)(g_h + (size_t)node0*DD);
      float4* dst = (float4*)sIn;
      for (int i = t; i < 32*DD/4; i += 256) dst[i] = src[i]; }
    __syncthreads();
    float4 acc[2];
    acc[0] = make_float4(0,0,0,0); acc[1] = make_float4(0,0,0,0);
    #pragma unroll 4
    for (int k = 0; k < DD; k += 4){
      const float4 w0 = *(const float4*)(sW1 + (k+0)*68 + d0);
      const float4 w1 = *(const float4*)(sW1 + (k+1)*68 + d0);
      const float4 w2 = *(const float4*)(sW1 + (k+2)*68 + d0);
      const float4 w3 = *(const float4*)(sW1 + (k+3)*68 + d0);
      #pragma unroll
      for (int j = 0; j < 2; j++){
        const float4 x = *(const float4*)(sIn + ((nG<<1)+j)*DD + k);
        fma4(acc[j], x, w0, w1, w2, w3);
      }
    }
    #pragma unroll
    for (int j = 0; j < 2; j++){
      float4 v = acc[j];
      v.x = lrelu(v.x + b1v.x); v.y = lrelu(v.y + b1v.y);
      v.z = lrelu(v.z + b1v.z); v.w = lrelu(v.w + b1v.w);
      *(float4*)(sU + ((nG<<1)+j)*64 + d0) = v;
    }
    __syncthreads();
    #pragma unroll
    for (int j = 0; j < 4; j++){
      const int nl = (warp<<2) + j;
      const float u0 = sU[nl*64 + lane];
      const float u1 = sU[nl*64 + lane + 32];
      float o0 = u0*sW2[lane*2]   + u1*sW2[(lane+32)*2];
      float o1 = u0*sW2[lane*2+1] + u1*sW2[(lane+32)*2+1];
      #pragma unroll
      for (int o = 16; o; o >>= 1){
        o0 += __shfl_xor_sync(0xffffffffu, o0, o);
        o1 += __shfl_xor_sync(0xffffffffu, o1, o);
      }
      if (lane == 0){
        out[(size_t)(node0 + nl)*2]     = o0 + sW2[128];
        out[(size_t)(node0 + nl)*2 + 1] = o1 + sW2[129];
      }
    }
    __syncthreads();
  }
}

// ---------------- host -------------------------------------------------------
extern "C" void kernel_launch(void* const* d_in, const int* in_sizes, int n_in,
                              void* d_out, int out_size){
  const float* x      = (const float*)d_in[0];
  const float* ea     = (const float*)d_in[1];
  const int*   ei     = (const int*)  d_in[2];
  const float* enc_W  = (const float*)d_in[3];
  const float* enc_b  = (const float*)d_in[4];
  const float* msg_W1 = (const float*)d_in[5];
  const float* msg_b1 = (const float*)d_in[6];
  const float* msg_lg = (const float*)d_in[7];
  const float* msg_lb = (const float*)d_in[8];
  const float* msg_W2 = (const float*)d_in[9];
  const float* msg_b2 = (const float*)d_in[10];
  const float* up_W   = (const float*)d_in[11];
  const float* up_b   = (const float*)d_in[12];
  const float* up_lg  = (const float*)d_in[13];
  const float* up_lb  = (const float*)d_in[14];
  const float* gc_Wa  = (const float*)d_in[15];
  const float* gc_ba  = (const float*)d_in[16];
  const float* gc_Wb  = (const float*)d_in[17];
  const float* gc_bb  = (const float*)d_in[18];
  const float* gc_Wc  = (const float*)d_in[19];
  const float* gc_bc  = (const float*)d_in[20];
  const float* dec_W1 = (const float*)d_in[21];
  const float* dec_b1 = (const float*)d_in[22];
  const float* dec_W2 = (const float*)d_in[23];
  const float* dec_b2 = (const float*)d_in[24];
  float* out = (float*)d_out;

  void *p_h, *p_P, *p_Q, *p_aggr, *p_gs, *p_deg, *p_W2u, *p_b2u;
  cudaGetSymbolAddress(&p_h, g_h);
  cudaGetSymbolAddress(&p_P, g_P);
  cudaGetSymbolAddress(&p_Q, g_Q);
  cudaGetSymbolAddress(&p_aggr, g_aggr);
  cudaGetSymbolAddress(&p_gs, g_gs);
  cudaGetSymbolAddress(&p_deg, g_deg);
  cudaGetSymbolAddress(&p_W2u, g_W2u);
  cudaGetSymbolAddress(&p_b2u, g_b2u);

  const int SM_MPQ = 6*128*SPAD*2;                        // 208896
  const int SM_MUP = 512*4 + 6*128*SPAD*2;                // 210944
  const int SM_GC  = (DD*WPAD + TILE*DD + 8*DD) * 4;      //  88064
  const int SM_DEC = (DD*68 + 32*DD + 32*64 + 130) * 4;   //  59912
  cudaFuncSetAttribute(k_mmaPQ, cudaFuncAttributeMaxDynamicSharedMemorySize, SM_MPQ);
  cudaFuncSetAttribute(k_mmaUP, cudaFuncAttributeMaxDynamicSharedMemorySize, SM_MUP);
  cudaFuncSetAttribute(k_gc,    cudaFuncAttributeMaxDynamicSharedMemorySize, SM_GC);
  cudaFuncSetAttribute(k_dec,   cudaFuncAttributeMaxDynamicSharedMemorySize, SM_DEC);

  cudaMemsetAsync(p_deg, 0, NN*sizeof(int), 0);
  k_encoder<<<BN, DD>>>(x, enc_W, enc_b);
  k_deg<<<(EE + 255)/256, 256>>>(ei);
  k_scan<<<1, 1024>>>();
  k_scatter<<<(EE + 255)/256, 256>>>(ei, ea);
  { dim3 g(NLAYERS, DD+1); k_prew2<<<g, DD>>>(msg_W2, msg_b2, up_W); }

  for (int l = 0; l < NLAYERS; l++){
    const float* W1  = msg_W1 + (size_t)l*258*DD;
    const float* W1a = W1;
    const float* W1b = W1 + 128*DD;
    const float* W1c = W1 + 256*DD;
    const float* b1  = msg_b1 + l*DD;
    const float* mlg = msg_lg + l*DD;
    const float* mlb = msg_lb + l*DD;
    const float* uWl = up_W  + (size_t)l*256*DD;
    const float* ubl = up_b  + l*DD;
    const float* ulg = up_lg + l*DD;
    const float* ulb = up_lb + l*DD;
    const float* Wa  = gc_Wa + (size_t)l*DD*DD;
    const float* ba  = gc_ba + l*DD;
    const float* Wb  = gc_Wb + (size_t)l*DD*DD;
    const float* bbv = gc_bb + l*DD;
    const float* Wc  = gc_Wc + (size_t)l*DD*DD;
    const float* bc  = gc_bc + l*DD;
    const float* W2u = (const float*)p_W2u + (size_t)l*DD*DD;
    const float* b2u = (const float*)p_b2u + (size_t)l*DD;

    cudaMemsetAsync(p_gs, 0, BB*DD*sizeof(float), 0);

    k_mmaPQ<<<148, 256, SM_MPQ>>>((const float*)p_h, W1a, W1b, (float*)p_P, (float*)p_Q);
    k_aggregate<<<(BB*NN)/8, 256>>>((const float*)p_P, (const float*)p_Q,
                                    W1c, b1, mlg, mlb, (float*)p_aggr);
    k_mmaUP<<<148, 256, SM_MUP>>>((const float*)p_aggr, uWl, W2u, b2u, ubl, ulg, ulb);
    k_gc<<<148, 256, SM_GC>>>((const float*)p_h, Wa, ba);
    k_gate<<<BB, DD>>>(Wb, bbv, Wc, bc);
    k_scale<<<(BN*DD + 255)/256, 256>>>();
  }

  k_dec<<<148, 256, SM_DEC>>>(dec_W1, dec_b1, dec_W2, dec_b2, out);
}